// round 5
// baseline (speedup 1.0000x reference)
#include <cuda_runtime.h>
#include <math.h>
#include <stdint.h>

#define S_TOK 257
#define D_DIM 1024
#define HID 4096
#define NLAYER 12
#define NC 256
#define CSZ 128
#define AGE_V 258
#define OBS_N 2048
#define OUT_N 512
#define HEADS 16
#define DH 64

// ---------------- scratch (device globals; no allocation allowed) ----------
__device__ float g_x[S_TOK * D_DIM];
__device__ float g_q[S_TOK * D_DIM];
__device__ float g_k[S_TOK * D_DIM];
__device__ float g_v[S_TOK * D_DIM];
__device__ float g_ao[S_TOK * D_DIM];
__device__ float g_ffn[S_TOK * HID];
__device__ float g_part[4 * S_TOK * D_DIM];   // split-K partials (KS<=4)

// ---------------- helpers ---------------------------------------------------
__device__ __forceinline__ float warpMax(float v) {
#pragma unroll
    for (int o = 16; o; o >>= 1) v = fmaxf(v, __shfl_xor_sync(0xffffffffu, v, o));
    return v;
}
__device__ __forceinline__ float warpSum(float v) {
#pragma unroll
    for (int o = 16; o; o >>= 1) v += __shfl_xor_sync(0xffffffffu, v, o);
    return v;
}
__device__ __forceinline__ uint32_t f2tf(float f) {
    uint32_t u;
    asm("cvt.rna.tf32.f32 %0, %1;" : "=r"(u) : "f"(f));
    return u;
}
__device__ __forceinline__ void mma1688(float (&d)[4], const uint32_t (&a)[4], const uint32_t (&b)[2]) {
    asm volatile(
        "mma.sync.aligned.m16n8k8.row.col.f32.tf32.tf32.f32 "
        "{%0,%1,%2,%3}, {%4,%5,%6,%7}, {%8,%9}, {%0,%1,%2,%3};\n"
        : "+f"(d[0]), "+f"(d[1]), "+f"(d[2]), "+f"(d[3])
        : "r"(a[0]), "r"(a[1]), "r"(a[2]), "r"(a[3]), "r"(b[0]), "r"(b[1]));
}

// ============================================================================
// tf32 GEMM, fragment-packed smem.
// Block 128x64, BK=32, 256 threads (8 warps 4x2, warp tile 32x32).
// Smem layout stores each thread's MMA fragment as ONE uint4:
//   A: v = {A[r][k], A[r+8][k], A[r][k+4], A[r+8][k+4]}   (tf32 bits)
//   B: v = {B[c][k], B[c][k+4], B[c+8][k], B[c+8][k+4]}
// Reader: 4 LDS.128 + 8 MMA per 8-k chunk (was 16 LDS.32).
// Double-buffered, register-staged prefetch, one __syncthreads per k-tile.
// ============================================================================
#define A4 1024   // uint4s per A buffer (128 rows x 32 k)
#define B4 512    // uint4s per B buffer ( 64 rows x 32 k)

__device__ __forceinline__ void tf32_core_packed(
    const float* __restrict__ A, const float* __restrict__ B,
    int M, int K, int bm, int bn, int kbeg, int ktiles,
    float (&acc)[2][4][4], uint4* __restrict__ As, uint4* __restrict__ Bs)
{
    const int tid = threadIdx.x;
    const int lane = tid & 31, wid = tid >> 5;
    const int wm = wid & 3, wn = wid >> 2;

    // ---- writer mapping: A (all 256 threads, one (row-pair, k-chunk) each)
    const int a_kc = tid >> 6;            // 0..3
    const int a_idx = tid & 63;           // 0..63
    const int a_g = a_idx >> 3, a_fr = a_idx & 7;
    const int a_row0 = bm + a_g * 16 + a_fr;
    const bool av0 = a_row0 < M, av1 = (a_row0 + 8) < M;
    const float* Ap0 = A + (size_t)a_row0 * K + kbeg + a_kc * 8;
    const float* Ap1 = Ap0 + (size_t)8 * K;
    const int a_dst = (a_g * 4 + a_kc) * 32 + a_fr * 4;

    // ---- writer mapping: B (threads 0..127)
    const int b_kc = (tid >> 5) & 3;
    const int b_idx = tid & 31;
    const int b_g = b_idx >> 3, b_fr = b_idx & 7;
    const int b_c0 = bn + b_g * 16 + b_fr;
    const float* Bp0 = B + (size_t)b_c0 * K + kbeg + b_kc * 8;
    const float* Bp1 = Bp0 + (size_t)8 * K;
    const int b_dst = (b_g * 4 + b_kc) * 32 + b_fr * 4;
    const bool bact = tid < 128;

    const float4 z4 = make_float4(0.f, 0.f, 0.f, 0.f);
    float4 a0a, a0b, a1a, a1b, b0a, b0b, b1a, b1b;

    // prologue: load tile 0
    a0a = av0 ? *(const float4*)(Ap0) : z4;
    a0b = av0 ? *(const float4*)(Ap0 + 4) : z4;
    a1a = av1 ? *(const float4*)(Ap1) : z4;
    a1b = av1 ? *(const float4*)(Ap1 + 4) : z4;
    if (bact) {
        b0a = *(const float4*)(Bp0);
        b0b = *(const float4*)(Bp0 + 4);
        b1a = *(const float4*)(Bp1);
        b1b = *(const float4*)(Bp1 + 4);
    }
    // pack into buffer 0
    {
        uint4* Ad = As + a_dst;
        Ad[0] = make_uint4(f2tf(a0a.x), f2tf(a1a.x), f2tf(a0b.x), f2tf(a1b.x));
        Ad[1] = make_uint4(f2tf(a0a.y), f2tf(a1a.y), f2tf(a0b.y), f2tf(a1b.y));
        Ad[2] = make_uint4(f2tf(a0a.z), f2tf(a1a.z), f2tf(a0b.z), f2tf(a1b.z));
        Ad[3] = make_uint4(f2tf(a0a.w), f2tf(a1a.w), f2tf(a0b.w), f2tf(a1b.w));
        if (bact) {
            uint4* Bd = Bs + b_dst;
            Bd[0] = make_uint4(f2tf(b0a.x), f2tf(b0b.x), f2tf(b1a.x), f2tf(b1b.x));
            Bd[1] = make_uint4(f2tf(b0a.y), f2tf(b0b.y), f2tf(b1a.y), f2tf(b1b.y));
            Bd[2] = make_uint4(f2tf(b0a.z), f2tf(b0b.z), f2tf(b1a.z), f2tf(b1b.z));
            Bd[3] = make_uint4(f2tf(b0a.w), f2tf(b0b.w), f2tf(b1a.w), f2tf(b1b.w));
        }
    }
    __syncthreads();

    int buf = 0;
    for (int kt = 0; kt < ktiles; kt++) {
        const bool hn = (kt + 1 < ktiles);
        if (hn) {
            const int off = (kt + 1) * 32;
            a0a = av0 ? *(const float4*)(Ap0 + off) : z4;
            a0b = av0 ? *(const float4*)(Ap0 + off + 4) : z4;
            a1a = av1 ? *(const float4*)(Ap1 + off) : z4;
            a1b = av1 ? *(const float4*)(Ap1 + off + 4) : z4;
            if (bact) {
                b0a = *(const float4*)(Bp0 + off);
                b0b = *(const float4*)(Bp0 + off + 4);
                b1a = *(const float4*)(Bp1 + off);
                b1b = *(const float4*)(Bp1 + off + 4);
            }
        }
        const uint4* Ab = As + buf * A4;
        const uint4* Bb = Bs + buf * B4;
#pragma unroll
        for (int kc = 0; kc < 4; kc++) {
            const uint4 va0 = Ab[((wm * 2 + 0) * 4 + kc) * 32 + lane];
            const uint4 va1 = Ab[((wm * 2 + 1) * 4 + kc) * 32 + lane];
            const uint4 vb0 = Bb[((wn * 2 + 0) * 4 + kc) * 32 + lane];
            const uint4 vb1 = Bb[((wn * 2 + 1) * 4 + kc) * 32 + lane];
            const uint32_t af0[4] = {va0.x, va0.y, va0.z, va0.w};
            const uint32_t af1[4] = {va1.x, va1.y, va1.z, va1.w};
            const uint32_t bf0[2] = {vb0.x, vb0.y};
            const uint32_t bf1[2] = {vb0.z, vb0.w};
            const uint32_t bf2[2] = {vb1.x, vb1.y};
            const uint32_t bf3[2] = {vb1.z, vb1.w};
            mma1688(acc[0][0], af0, bf0);
            mma1688(acc[0][1], af0, bf1);
            mma1688(acc[0][2], af0, bf2);
            mma1688(acc[0][3], af0, bf3);
            mma1688(acc[1][0], af1, bf0);
            mma1688(acc[1][1], af1, bf1);
            mma1688(acc[1][2], af1, bf2);
            mma1688(acc[1][3], af1, bf3);
        }
        if (hn) {
            const int nb = buf ^ 1;
            uint4* Ad = As + nb * A4 + a_dst;
            Ad[0] = make_uint4(f2tf(a0a.x), f2tf(a1a.x), f2tf(a0b.x), f2tf(a1b.x));
            Ad[1] = make_uint4(f2tf(a0a.y), f2tf(a1a.y), f2tf(a0b.y), f2tf(a1b.y));
            Ad[2] = make_uint4(f2tf(a0a.z), f2tf(a1a.z), f2tf(a0b.z), f2tf(a1b.z));
            Ad[3] = make_uint4(f2tf(a0a.w), f2tf(a1a.w), f2tf(a0b.w), f2tf(a1b.w));
            if (bact) {
                uint4* Bd = Bs + nb * B4 + b_dst;
                Bd[0] = make_uint4(f2tf(b0a.x), f2tf(b0b.x), f2tf(b1a.x), f2tf(b1b.x));
                Bd[1] = make_uint4(f2tf(b0a.y), f2tf(b0b.y), f2tf(b1a.y), f2tf(b1b.y));
                Bd[2] = make_uint4(f2tf(b0a.z), f2tf(b0b.z), f2tf(b1a.z), f2tf(b1b.z));
                Bd[3] = make_uint4(f2tf(b0a.w), f2tf(b0b.w), f2tf(b1a.w), f2tf(b1b.w));
            }
            __syncthreads();
            buf = nb;
        }
    }
}

// ---- epilogue helper macros (acc layout shared by all GEMM kernels) --------
#define GEMM_EPI_VARS \
    const int lane = threadIdx.x & 31, wid = threadIdx.x >> 5; \
    const int wm = wid & 3, wn = wid >> 2; \
    const int fr = lane >> 2, fc = lane & 3;

// ---- fused QKV ---------------------------------------------------------------
__global__ __launch_bounds__(256) void gemm_qkv_kernel(
    const float* __restrict__ A,
    const float* __restrict__ Wq_, const float* __restrict__ Wk_, const float* __restrict__ Wv_,
    const float* __restrict__ bq_, const float* __restrict__ bk_, const float* __restrict__ bv_,
    float* __restrict__ Q, float* __restrict__ Ko, float* __restrict__ V,
    int M, int N, int K)
{
    __shared__ uint4 AsS[2 * A4];
    __shared__ uint4 BsS[2 * B4];
    const int z = blockIdx.z;
    const float* B    = (z == 0) ? Wq_ : (z == 1) ? Wk_ : Wv_;
    const float* bias = (z == 0) ? bq_ : (z == 1) ? bk_ : bv_;
    float* C          = (z == 0) ? Q   : (z == 1) ? Ko  : V;

    const int bm = blockIdx.y * 128;
    const int bn = blockIdx.x * 64;
    float acc[2][4][4] = {};
    tf32_core_packed(A, B, M, K, bm, bn, 0, K / 32, acc, AsS, BsS);

    GEMM_EPI_VARS
#pragma unroll
    for (int mi = 0; mi < 2; mi++)
#pragma unroll
        for (int ni = 0; ni < 4; ni++) {
            const int r = bm + wm * 32 + mi * 16 + fr;
            const int c = bn + wn * 32 + ni * 8 + fc * 2;
            const float bx = bias[c], by = bias[c + 1];
            if (r < M) {
                float2 o = {acc[mi][ni][0] + bx, acc[mi][ni][1] + by};
                *(float2*)(C + (size_t)r * N + c) = o;
            }
            if (r + 8 < M) {
                float2 o = {acc[mi][ni][2] + bx, acc[mi][ni][3] + by};
                *(float2*)(C + (size_t)(r + 8) * N + c) = o;
            }
        }
}

// ---- direct GEMM with bias (+relu) -------------------------------------------
__global__ __launch_bounds__(256) void gemm_direct_kernel(
    const float* __restrict__ A, const float* __restrict__ B,
    const float* __restrict__ bias, float* __restrict__ C,
    int M, int N, int K, int relu_flag)
{
    __shared__ uint4 AsS[2 * A4];
    __shared__ uint4 BsS[2 * B4];
    const int bm = blockIdx.y * 128;
    const int bn = blockIdx.x * 64;
    float acc[2][4][4] = {};
    tf32_core_packed(A, B, M, K, bm, bn, 0, K / 32, acc, AsS, BsS);

    GEMM_EPI_VARS
#pragma unroll
    for (int mi = 0; mi < 2; mi++)
#pragma unroll
        for (int ni = 0; ni < 4; ni++) {
            const int r = bm + wm * 32 + mi * 16 + fr;
            const int c = bn + wn * 32 + ni * 8 + fc * 2;
            const float bx = bias[c], by = bias[c + 1];
            if (r < M) {
                float2 o = {acc[mi][ni][0] + bx, acc[mi][ni][1] + by};
                if (relu_flag) { o.x = fmaxf(o.x, 0.f); o.y = fmaxf(o.y, 0.f); }
                *(float2*)(C + (size_t)r * N + c) = o;
            }
            if (r + 8 < M) {
                float2 o = {acc[mi][ni][2] + bx, acc[mi][ni][3] + by};
                if (relu_flag) { o.x = fmaxf(o.x, 0.f); o.y = fmaxf(o.y, 0.f); }
                *(float2*)(C + (size_t)(r + 8) * N + c) = o;
            }
        }
}

// ---- split-K GEMM (raw partials) ---------------------------------------------
__global__ __launch_bounds__(256) void gemm_splitk_kernel(
    const float* __restrict__ A, const float* __restrict__ B,
    float* __restrict__ part, int M, int N, int K, int klen)
{
    __shared__ uint4 AsS[2 * A4];
    __shared__ uint4 BsS[2 * B4];
    const int bm = blockIdx.y * 128;
    const int bn = blockIdx.x * 64;
    const int z = blockIdx.z;
    float acc[2][4][4] = {};
    tf32_core_packed(A, B, M, K, bm, bn, z * klen, klen / 32, acc, AsS, BsS);

    float* C = part + (size_t)z * M * N;
    GEMM_EPI_VARS
#pragma unroll
    for (int mi = 0; mi < 2; mi++)
#pragma unroll
        for (int ni = 0; ni < 4; ni++) {
            const int r = bm + wm * 32 + mi * 16 + fr;
            const int c = bn + wn * 32 + ni * 8 + fc * 2;
            if (r < M) {
                float2 o = {acc[mi][ni][0], acc[mi][ni][1]};
                *(float2*)(C + (size_t)r * N + c) = o;
            }
            if (r + 8 < M) {
                float2 o = {acc[mi][ni][2], acc[mi][ni][3]};
                *(float2*)(C + (size_t)(r + 8) * N + c) = o;
            }
        }
}

// ---- fused combine(split-K) + bias + residual + LayerNorm --------------------
__global__ __launch_bounds__(256) void combine_ln_kernel(
    const float* __restrict__ part, int KS,
    const float* __restrict__ bias, const float* __restrict__ res,
    const float* __restrict__ g, const float* __restrict__ b,
    float* __restrict__ out, int M)
{
    const int row = blockIdx.x;
    const int tid = threadIdx.x;
    const int lane = tid & 31, warp = tid >> 5;
    __shared__ float rs[8], rs2[8];
    __shared__ float smv[2];

    float4 s = ((const float4*)(part + (size_t)row * D_DIM))[tid];
    for (int z = 1; z < KS; z++) {
        const float4 t = ((const float4*)(part + ((size_t)z * M + row) * D_DIM))[tid];
        s.x += t.x; s.y += t.y; s.z += t.z; s.w += t.w;
    }
    const float4 b4 = ((const float4*)bias)[tid];
    s.x += b4.x; s.y += b4.y; s.z += b4.z; s.w += b4.w;
    const float4 r4 = ((const float4*)(res + (size_t)row * D_DIM))[tid];
    s.x += r4.x; s.y += r4.y; s.z += r4.z; s.w += r4.w;

    float sum = s.x + s.y + s.z + s.w;
    float sq = s.x * s.x + s.y * s.y + s.z * s.z + s.w * s.w;
    sum = warpSum(sum); sq = warpSum(sq);
    if (lane == 0) { rs[warp] = sum; rs2[warp] = sq; }
    __syncthreads();
    if (warp == 0) {
        float t = (lane < 8) ? rs[lane] : 0.f;
        float t2 = (lane < 8) ? rs2[lane] : 0.f;
        t = warpSum(t); t2 = warpSum(t2);
        if (lane == 0) {
            const float mean = t * (1.0f / D_DIM);
            const float var = t2 * (1.0f / D_DIM) - mean * mean;
            smv[0] = mean;
            smv[1] = rsqrtf(var + 1e-5f);
        }
    }
    __syncthreads();
    const float mean = smv[0], inv = smv[1];
    const float4 g4 = ((const float4*)g)[tid];
    const float4 be4 = ((const float4*)b)[tid];
    float4 o;
    o.x = (s.x - mean) * inv * g4.x + be4.x;
    o.y = (s.y - mean) * inv * g4.y + be4.y;
    o.z = (s.z - mean) * inv * g4.z + be4.z;
    o.w = (s.w - mean) * inv * g4.w + be4.w;
    ((float4*)(out + (size_t)row * D_DIM))[tid] = o;
}

// ---------------- attention: block per (head, 16-query tile) ----------------
#define QT 16
__global__ __launch_bounds__(256) void attn3_kernel(
    const float* __restrict__ q, const float* __restrict__ k,
    const float* __restrict__ v, float* __restrict__ o)
{
    const int h = blockIdx.x;
    const int qt = blockIdx.y * QT;
    const int tid = threadIdx.x, lane = tid & 31, warp = tid >> 5;

    __shared__ float Qs[QT][68];
    __shared__ float T[64][68];
    __shared__ float sc[QT][261];
    __shared__ float inv_s[QT];

    const int nq = min(QT, S_TOK - qt);

    {
        const int r = tid >> 4, c4 = (tid & 15) << 2;
        float4 val = (r < nq) ? *(const float4*)(q + (size_t)(qt + r) * D_DIM + h * DH + c4)
                              : make_float4(0.f, 0.f, 0.f, 0.f);
        *(float4*)&Qs[r][c4] = val;
    }

    const int qrow = tid & 15, jg = tid >> 4;

    for (int j0 = 0; j0 < S_TOK; j0 += 64) {
        const int jn = min(64, S_TOK - j0);
        __syncthreads();
#pragma unroll
        for (int i = 0; i < 4; i++) {
            const int idx = tid + i * 256;
            const int r = idx >> 4, c4 = (idx & 15) << 2;
            float4 val = (r < jn) ? *(const float4*)(k + (size_t)(j0 + r) * D_DIM + h * DH + c4)
                                  : make_float4(0.f, 0.f, 0.f, 0.f);
            *(float4*)&T[r][c4] = val;
        }
        __syncthreads();
        for (int jj = jg; jj < jn; jj += 16) {
            const float4* qr4 = (const float4*)Qs[qrow];
            const float4* kr4 = (const float4*)T[jj];
            float s = 0.f;
#pragma unroll
            for (int t = 0; t < 16; t++) {
                const float4 a = qr4[t], bb = kr4[t];
                s += a.x * bb.x + a.y * bb.y + a.z * bb.z + a.w * bb.w;
            }
            sc[qrow][j0 + jj] = s * 0.125f;
        }
    }
    __syncthreads();

#pragma unroll
    for (int ri = 0; ri < 2; ri++) {
        const int r = warp * 2 + ri;
        if (r < nq) {
            float m = -1e30f;
            for (int j = lane; j < S_TOK; j += 32) m = fmaxf(m, sc[r][j]);
            m = warpMax(m);
            float ssum = 0.f;
            for (int j = lane; j < S_TOK; j += 32) {
                const float e = __expf(sc[r][j] - m);
                sc[r][j] = e;
                ssum += e;
            }
            ssum = warpSum(ssum);
            if (lane == 0) inv_s[r] = 1.0f / ssum;
        }
    }
    __syncthreads();

    const int db = (tid >> 4) << 2;
    float4 acc = make_float4(0.f, 0.f, 0.f, 0.f);
    for (int j0 = 0; j0 < S_TOK; j0 += 64) {
        const int jn = min(64, S_TOK - j0);
        __syncthreads();
#pragma unroll
        for (int i = 0; i < 4; i++) {
            const int idx = tid + i * 256;
            const int r = idx >> 4, c4 = (idx & 15) << 2;
            float4 val = (r < jn) ? *(const float4*)(v + (size_t)(j0 + r) * D_DIM + h * DH + c4)
                                  : make_float4(0.f, 0.f, 0.f, 0.f);
            *(float4*)&T[r][c4] = val;
        }
        __syncthreads();
        for (int jj = 0; jj < jn; jj++) {
            const float w = sc[qrow][j0 + jj];
            const float4 vv = *(const float4*)&T[jj][db];
            acc.x += w * vv.x; acc.y += w * vv.y; acc.z += w * vv.z; acc.w += w * vv.w;
        }
    }
    if (qrow < nq) {
        const float iv = inv_s[qrow];
        float4 oo = {acc.x * iv, acc.y * iv, acc.z * iv, acc.w * iv};
        *(float4*)(o + (size_t)(qt + qrow) * D_DIM + h * DH + db) = oo;
    }
}

// ---------------- matvec (embeddings / heads) -------------------------------
__global__ __launch_bounds__(256) void matvec_kernel(
    const float* __restrict__ W, const float* __restrict__ bias,
    const float* __restrict__ x, float* __restrict__ out,
    int N, int K, int act)
{
    __shared__ float xs[OBS_N];
    const int tid = threadIdx.x;
    for (int i = tid; i < K; i += 256) xs[i] = x[i];
    __syncthreads();
    const int warp = tid >> 5, lane = tid & 31;
    const int n = blockIdx.x * 8 + warp;
    if (n >= N) return;
    const float4* wr = reinterpret_cast<const float4*>(W + (size_t)n * K);
    const float4* x4 = reinterpret_cast<const float4*>(xs);
    float s = 0.f;
    const int K4 = K >> 2;
    for (int kb = lane; kb < K4; kb += 32) {
        const float4 w = wr[kb], xv = x4[kb];
        s += w.x * xv.x + w.y * xv.y + w.z * xv.z + w.w * xv.w;
    }
    s = warpSum(s);
    if (lane == 0) {
        s += bias[n];
        if (act == 1) s = fmaxf(s, 0.f);
        else if (act == 2) s = tanhf(s);
        out[n] = s;
    }
}

// ---------------- concept embedding (rows 1..256 of x) ---------------------
__global__ __launch_bounds__(256) void cemb_kernel(
    const float* __restrict__ concepts, const float* __restrict__ Wc,
    const float* __restrict__ bc, const float* __restrict__ Wage,
    const float* __restrict__ bage, float* __restrict__ x)
{
    const int i = blockIdx.x;
    const int tid = threadIdx.x;
    __shared__ float cv[CSZ];
    if (tid < CSZ) cv[tid] = concepts[i * CSZ + tid];
    __syncthreads();
    const float agef = (float)i / 256.0f;
    for (int d = tid; d < D_DIM; d += 256) {
        const float4* wr = reinterpret_cast<const float4*>(Wc + (size_t)d * CSZ);
        const float4* c4 = reinterpret_cast<const float4*>(cv);
        float s = 0.f;
#pragma unroll
        for (int t = 0; t < CSZ / 4; t++) {
            const float4 w = wr[t], c = c4[t];
            s += w.x * c.x + w.y * c.y + w.z * c.z + w.w * c.w;
        }
        s += bc[d] + Wage[(size_t)d * AGE_V + i] + agef * Wage[(size_t)d * AGE_V + (AGE_V - 1)] + bage[d];
        x[(size_t)(i + 1) * D_DIM + d] = s;
    }
}

// ---------------- host launch ----------------------------------------------
extern "C" void kernel_launch(void* const* d_in, const int* in_sizes, int n_in,
                              void* d_out, int out_size)
{
    const float* observation = (const float*)d_in[0];
    const float* concepts    = (const float*)d_in[1];
    const float* W_core = (const float*)d_in[2];
    const float* b_core = (const float*)d_in[3];
    const float* W_cemb = (const float*)d_in[4];
    const float* b_cemb = (const float*)d_in[5];
    const float* W_age  = (const float*)d_in[6];
    const float* b_age  = (const float*)d_in[7];
    const float* Wq = (const float*)d_in[8];
    const float* bq = (const float*)d_in[9];
    const float* Wk = (const float*)d_in[10];
    const float* bk = (const float*)d_in[11];
    const float* Wv = (const float*)d_in[12];
    const float* bv = (const float*)d_in[13];
    const float* Wo = (const float*)d_in[14];
    const float* bo = (const float*)d_in[15];
    const float* ln1_g = (const float*)d_in[16];
    const float* ln1_b = (const float*)d_in[17];
    const float* W1 = (const float*)d_in[18];
    const float* b1 = (const float*)d_in[19];
    const float* W2 = (const float*)d_in[20];
    const float* b2 = (const float*)d_in[21];
    const float* ln2_g = (const float*)d_in[22];
    const float* ln2_b = (const float*)d_in[23];
    const float* W_concept = (const float*)d_in[24];
    const float* b_concept = (const float*)d_in[25];
    const float* W_out = (const float*)d_in[26];
    const float* b_out = (const float*)d_in[27];

    float *x, *q, *k, *v, *ao, *ffn, *part;
    cudaGetSymbolAddress((void**)&x, g_x);
    cudaGetSymbolAddress((void**)&q, g_q);
    cudaGetSymbolAddress((void**)&k, g_k);
    cudaGetSymbolAddress((void**)&v, g_v);
    cudaGetSymbolAddress((void**)&ao, g_ao);
    cudaGetSymbolAddress((void**)&ffn, g_ffn);
    cudaGetSymbolAddress((void**)&part, g_part);

    const int M = S_TOK;
    const dim3 blk(256);
    const int MT = (M + 127) / 128;               // 3 m-tiles
    const dim3 grid_qkv(D_DIM / 64, MT, 3);       // 144 blocks
    const dim3 grid_o(D_DIM / 64, MT, 4);         // split-K=4, 192 blocks
    const dim3 grid_w1(HID / 64, MT, 1);          // 192 blocks
    const dim3 grid_w2(D_DIM / 64, MT, 4);        // split-K=4, 192 blocks
    const dim3 grid_attn(HEADS, (S_TOK + QT - 1) / QT);   // 16 x 17

    // --- embeddings ---
    matvec_kernel<<<D_DIM / 8, 256>>>(W_core, b_core, observation, x, D_DIM, OBS_N, 0);
    cemb_kernel<<<NC, 256>>>(concepts, W_cemb, b_cemb, W_age, b_age, x);

    // --- transformer layers ---
    for (int l = 0; l < NLAYER; l++) {
        const size_t od  = (size_t)l * D_DIM * D_DIM;
        const size_t ob  = (size_t)l * D_DIM;
        const size_t o1w = (size_t)l * HID * D_DIM;
        const size_t o1b = (size_t)l * HID;

        gemm_qkv_kernel<<<grid_qkv, blk>>>(
            x, Wq + od, Wk + od, Wv + od, bq + ob, bk + ob, bv + ob,
            q, k, v, M, D_DIM, D_DIM);

        attn3_kernel<<<grid_attn, blk>>>(q, k, v, ao);

        gemm_splitk_kernel<<<grid_o, blk>>>(
            ao, Wo + od, part, M, D_DIM, D_DIM, D_DIM / 4);
        combine_ln_kernel<<<M, 256>>>(part, 4, bo + ob, x, ln1_g + ob, ln1_b + ob, x, M);

        gemm_direct_kernel<<<grid_w1, blk>>>(
            x, W1 + o1w, b1 + o1b, ffn, M, HID, D_DIM, 1);
        gemm_splitk_kernel<<<grid_w2, blk>>>(
            ffn, W2 + o1w, part, M, D_DIM, HID, HID / 4);
        combine_ln_kernel<<<M, 256>>>(part, 4, b2 + ob, x, ln2_g + ob, ln2_b + ob, x, M);
    }

    // --- heads (node 0) -> d_out = [output(512) | new_concept(128)] ---
    float* out = (float*)d_out;
    matvec_kernel<<<OUT_N / 8, 256>>>(W_out, b_out, x, out, OUT_N, D_DIM, 1);
    matvec_kernel<<<CSZ / 8, 256>>>(W_concept, b_concept, x, out + OUT_N, CSZ, D_DIM, 2);

    (void)in_sizes; (void)n_in; (void)out_size;
}

// round 6
// speedup vs baseline: 1.8624x; 1.8624x over previous
#include <cuda_runtime.h>
#include <math.h>
#include <stdint.h>

#define S_TOK 257
#define D_DIM 1024
#define HID 4096
#define NLAYER 12
#define NC 256
#define CSZ 128
#define AGE_V 258
#define OBS_N 2048
#define OUT_N 512
#define HEADS 16
#define DH 64

// ---------------- scratch (device globals; no allocation allowed) ----------
__device__ float g_x[S_TOK * D_DIM];
__device__ float g_q[S_TOK * D_DIM];
__device__ float g_k[S_TOK * D_DIM];
__device__ float g_v[S_TOK * D_DIM];
__device__ float g_ao[S_TOK * D_DIM];
__device__ float g_ffn[S_TOK * HID];
__device__ float g_part[4 * S_TOK * D_DIM];   // split-K partials (KS<=4)

// ---------------- helpers ---------------------------------------------------
__device__ __forceinline__ float warpMax(float v) {
#pragma unroll
    for (int o = 16; o; o >>= 1) v = fmaxf(v, __shfl_xor_sync(0xffffffffu, v, o));
    return v;
}
__device__ __forceinline__ float warpSum(float v) {
#pragma unroll
    for (int o = 16; o; o >>= 1) v += __shfl_xor_sync(0xffffffffu, v, o);
    return v;
}
__device__ __forceinline__ uint32_t f2tf(float f) {
    uint32_t u;
    asm("cvt.rna.tf32.f32 %0, %1;" : "=r"(u) : "f"(f));
    return u;
}
__device__ __forceinline__ void mma1688(float (&d)[4], const uint32_t (&a)[4], const uint32_t (&b)[2]) {
    asm volatile(
        "mma.sync.aligned.m16n8k8.row.col.f32.tf32.tf32.f32 "
        "{%0,%1,%2,%3}, {%4,%5,%6,%7}, {%8,%9}, {%0,%1,%2,%3};\n"
        : "+f"(d[0]), "+f"(d[1]), "+f"(d[2]), "+f"(d[3])
        : "r"(a[0]), "r"(a[1]), "r"(a[2]), "r"(a[3]), "r"(b[0]), "r"(b[1]));
}

// ============================================================================
// tf32 GEMM core (Round-3 proven): C[M,N] = A[M,K] @ B[N,K]^T. Block 64x64,
// BK=32, 256 threads (8 warps 2x4, warp tile 32x16 via 2x2 m16n8k8).
// Coalesced global loads, smem stride 36, register-staged prefetch.
// ============================================================================
__device__ __forceinline__ void tf32_core(
    const float* __restrict__ A, const float* __restrict__ B,
    int M, int K, int bm, int bn, int kbeg, int ktiles,
    float (&acc)[2][2][4], uint32_t (*As)[36], uint32_t (*Bs)[36])
{
    const int tid = threadIdx.x;
    const int lane = tid & 31, wid = tid >> 5;
    const int wm = wid & 1, wn = wid >> 1;
    const int fr = lane >> 2, fc = lane & 3;

    int arow[2], akq[2];
    bool aval[2];
    const float* aptr[2];
    const float* bptr[2];
#pragma unroll
    for (int i = 0; i < 2; i++) {
        const int idx = tid + i * 256;
        const int row = idx >> 3, kq = (idx & 7) << 2;
        arow[i] = row; akq[i] = kq;
        aval[i] = (bm + row) < M;
        aptr[i] = A + (size_t)(bm + row) * K + kbeg + kq;
        bptr[i] = B + (size_t)(bn + row) * K + kbeg + kq;
    }

    float4 pa[2], pb[2];
#pragma unroll
    for (int i = 0; i < 2; i++) {
        pa[i] = aval[i] ? *(const float4*)(aptr[i]) : make_float4(0.f, 0.f, 0.f, 0.f);
        pb[i] = *(const float4*)(bptr[i]);
    }
#pragma unroll
    for (int i = 0; i < 2; i++) {
        *(uint4*)&As[arow[i]][akq[i]] = make_uint4(f2tf(pa[i].x), f2tf(pa[i].y), f2tf(pa[i].z), f2tf(pa[i].w));
        *(uint4*)&Bs[arow[i]][akq[i]] = make_uint4(f2tf(pb[i].x), f2tf(pb[i].y), f2tf(pb[i].z), f2tf(pb[i].w));
    }
    __syncthreads();

    for (int kt = 0; kt < ktiles; kt++) {
        const bool has_next = (kt + 1 < ktiles);
        if (has_next) {
            const int off = (kt + 1) * 32;
#pragma unroll
            for (int i = 0; i < 2; i++) {
                pa[i] = aval[i] ? *(const float4*)(aptr[i] + off) : make_float4(0.f, 0.f, 0.f, 0.f);
                pb[i] = *(const float4*)(bptr[i] + off);
            }
        }
#pragma unroll
        for (int k0 = 0; k0 < 32; k0 += 8) {
            uint32_t af[2][4], bf[2][2];
#pragma unroll
            for (int mi = 0; mi < 2; mi++) {
                const int r = wm * 32 + mi * 16 + fr;
                af[mi][0] = As[r][k0 + fc];
                af[mi][1] = As[r + 8][k0 + fc];
                af[mi][2] = As[r][k0 + fc + 4];
                af[mi][3] = As[r + 8][k0 + fc + 4];
            }
#pragma unroll
            for (int ni = 0; ni < 2; ni++) {
                const int c = wn * 16 + ni * 8 + fr;
                bf[ni][0] = Bs[c][k0 + fc];
                bf[ni][1] = Bs[c][k0 + fc + 4];
            }
#pragma unroll
            for (int mi = 0; mi < 2; mi++)
#pragma unroll
                for (int ni = 0; ni < 2; ni++)
                    mma1688(acc[mi][ni], af[mi], bf[ni]);
        }
        if (has_next) {
            __syncthreads();
#pragma unroll
            for (int i = 0; i < 2; i++) {
                *(uint4*)&As[arow[i]][akq[i]] = make_uint4(f2tf(pa[i].x), f2tf(pa[i].y), f2tf(pa[i].z), f2tf(pa[i].w));
                *(uint4*)&Bs[arow[i]][akq[i]] = make_uint4(f2tf(pb[i].x), f2tf(pb[i].y), f2tf(pb[i].z), f2tf(pb[i].w));
            }
            __syncthreads();
        }
    }
}

// ---- fused QKV ---------------------------------------------------------------
__global__ __launch_bounds__(256) void gemm_qkv_kernel(
    const float* __restrict__ A,
    const float* __restrict__ Wq_, const float* __restrict__ Wk_, const float* __restrict__ Wv_,
    const float* __restrict__ bq_, const float* __restrict__ bk_, const float* __restrict__ bv_,
    float* __restrict__ Q, float* __restrict__ Ko, float* __restrict__ V,
    int M, int N, int K)
{
    __shared__ uint32_t As[64][36];
    __shared__ uint32_t Bs[64][36];
    const int z = blockIdx.z;
    const float* B    = (z == 0) ? Wq_ : (z == 1) ? Wk_ : Wv_;
    const float* bias = (z == 0) ? bq_ : (z == 1) ? bk_ : bv_;
    float* C          = (z == 0) ? Q   : (z == 1) ? Ko  : V;

    const int bm = blockIdx.y * 64;
    const int bn = blockIdx.x * 64;
    float acc[2][2][4] = {};
    tf32_core(A, B, M, K, bm, bn, 0, K / 32, acc, As, Bs);

    const int lane = threadIdx.x & 31, wid = threadIdx.x >> 5;
    const int wm = wid & 1, wn = wid >> 1;
    const int fr = lane >> 2, fc = lane & 3;
#pragma unroll
    for (int mi = 0; mi < 2; mi++)
#pragma unroll
        for (int ni = 0; ni < 2; ni++) {
            const int r = bm + wm * 32 + mi * 16 + fr;
            const int c = bn + wn * 16 + ni * 8 + fc * 2;
            const float bx = bias[c], by = bias[c + 1];
            if (r < M) {
                float2 o = {acc[mi][ni][0] + bx, acc[mi][ni][1] + by};
                *(float2*)(C + (size_t)r * N + c) = o;
            }
            if (r + 8 < M) {
                float2 o = {acc[mi][ni][2] + bx, acc[mi][ni][3] + by};
                *(float2*)(C + (size_t)(r + 8) * N + c) = o;
            }
        }
}

// ---- direct GEMM with bias (+relu) -------------------------------------------
__global__ __launch_bounds__(256) void gemm_direct_kernel(
    const float* __restrict__ A, const float* __restrict__ B,
    const float* __restrict__ bias, float* __restrict__ C,
    int M, int N, int K, int relu_flag)
{
    __shared__ uint32_t As[64][36];
    __shared__ uint32_t Bs[64][36];
    const int bm = blockIdx.y * 64;
    const int bn = blockIdx.x * 64;
    float acc[2][2][4] = {};
    tf32_core(A, B, M, K, bm, bn, 0, K / 32, acc, As, Bs);

    const int lane = threadIdx.x & 31, wid = threadIdx.x >> 5;
    const int wm = wid & 1, wn = wid >> 1;
    const int fr = lane >> 2, fc = lane & 3;
#pragma unroll
    for (int mi = 0; mi < 2; mi++)
#pragma unroll
        for (int ni = 0; ni < 2; ni++) {
            const int r = bm + wm * 32 + mi * 16 + fr;
            const int c = bn + wn * 16 + ni * 8 + fc * 2;
            const float bx = bias[c], by = bias[c + 1];
            if (r < M) {
                float2 o = {acc[mi][ni][0] + bx, acc[mi][ni][1] + by};
                if (relu_flag) { o.x = fmaxf(o.x, 0.f); o.y = fmaxf(o.y, 0.f); }
                *(float2*)(C + (size_t)r * N + c) = o;
            }
            if (r + 8 < M) {
                float2 o = {acc[mi][ni][2] + bx, acc[mi][ni][3] + by};
                if (relu_flag) { o.x = fmaxf(o.x, 0.f); o.y = fmaxf(o.y, 0.f); }
                *(float2*)(C + (size_t)(r + 8) * N + c) = o;
            }
        }
}

// ---- split-K GEMM (raw partials) ---------------------------------------------
__global__ __launch_bounds__(256) void gemm_splitk_kernel(
    const float* __restrict__ A, const float* __restrict__ B,
    float* __restrict__ part, int M, int N, int K, int klen)
{
    __shared__ uint32_t As[64][36];
    __shared__ uint32_t Bs[64][36];
    const int bm = blockIdx.y * 64;
    const int bn = blockIdx.x * 64;
    const int z = blockIdx.z;
    float acc[2][2][4] = {};
    tf32_core(A, B, M, K, bm, bn, z * klen, klen / 32, acc, As, Bs);

    float* C = part + (size_t)z * M * N;
    const int lane = threadIdx.x & 31, wid = threadIdx.x >> 5;
    const int wm = wid & 1, wn = wid >> 1;
    const int fr = lane >> 2, fc = lane & 3;
#pragma unroll
    for (int mi = 0; mi < 2; mi++)
#pragma unroll
        for (int ni = 0; ni < 2; ni++) {
            const int r = bm + wm * 32 + mi * 16 + fr;
            const int c = bn + wn * 16 + ni * 8 + fc * 2;
            if (r < M) {
                float2 o = {acc[mi][ni][0], acc[mi][ni][1]};
                *(float2*)(C + (size_t)r * N + c) = o;
            }
            if (r + 8 < M) {
                float2 o = {acc[mi][ni][2], acc[mi][ni][3]};
                *(float2*)(C + (size_t)(r + 8) * N + c) = o;
            }
        }
}

// ---- fused combine(split-K) + bias + residual + LayerNorm --------------------
__global__ __launch_bounds__(256) void combine_ln_kernel(
    const float* __restrict__ part, int KS,
    const float* __restrict__ bias, const float* __restrict__ res,
    const float* __restrict__ g, const float* __restrict__ b,
    float* __restrict__ out, int M)
{
    const int row = blockIdx.x;
    const int tid = threadIdx.x;
    const int lane = tid & 31, warp = tid >> 5;
    __shared__ float rs[8], rs2[8];
    __shared__ float smv[2];

    float4 s = ((const float4*)(part + (size_t)row * D_DIM))[tid];
    for (int z = 1; z < KS; z++) {
        const float4 t = ((const float4*)(part + ((size_t)z * M + row) * D_DIM))[tid];
        s.x += t.x; s.y += t.y; s.z += t.z; s.w += t.w;
    }
    const float4 b4 = ((const float4*)bias)[tid];
    s.x += b4.x; s.y += b4.y; s.z += b4.z; s.w += b4.w;
    const float4 r4 = ((const float4*)(res + (size_t)row * D_DIM))[tid];
    s.x += r4.x; s.y += r4.y; s.z += r4.z; s.w += r4.w;

    float sum = s.x + s.y + s.z + s.w;
    float sq = s.x * s.x + s.y * s.y + s.z * s.z + s.w * s.w;
    sum = warpSum(sum); sq = warpSum(sq);
    if (lane == 0) { rs[warp] = sum; rs2[warp] = sq; }
    __syncthreads();
    if (warp == 0) {
        float t = (lane < 8) ? rs[lane] : 0.f;
        float t2 = (lane < 8) ? rs2[lane] : 0.f;
        t = warpSum(t); t2 = warpSum(t2);
        if (lane == 0) {
            const float mean = t * (1.0f / D_DIM);
            const float var = t2 * (1.0f / D_DIM) - mean * mean;
            smv[0] = mean;
            smv[1] = rsqrtf(var + 1e-5f);
        }
    }
    __syncthreads();
    const float mean = smv[0], inv = smv[1];
    const float4 g4 = ((const float4*)g)[tid];
    const float4 be4 = ((const float4*)b)[tid];
    float4 o;
    o.x = (s.x - mean) * inv * g4.x + be4.x;
    o.y = (s.y - mean) * inv * g4.y + be4.y;
    o.z = (s.z - mean) * inv * g4.z + be4.z;
    o.w = (s.w - mean) * inv * g4.w + be4.w;
    ((float4*)(out + (size_t)row * D_DIM))[tid] = o;
}

// ---------------- attention: block per (head, 16-query tile) ----------------
// sc padded to 325 cols (odd*?: 325 mod 32 = 5 -> conflict-free scalar rows);
// cols [257..320) zeroed so phase-3 can run unguarded 4x-unrolled.
#define QT 16
#define SC_W 325
__global__ __launch_bounds__(256) void attn3_kernel(
    const float* __restrict__ q, const float* __restrict__ k,
    const float* __restrict__ v, float* __restrict__ o)
{
    const int h = blockIdx.x;
    const int qt = blockIdx.y * QT;
    const int tid = threadIdx.x, lane = tid & 31, warp = tid >> 5;

    __shared__ float Qs[QT][68];
    __shared__ float T[64][68];
    __shared__ float sc[QT][SC_W];
    __shared__ float inv_s[QT];

    const int nq = min(QT, S_TOK - qt);

    // load Q tile (256 threads = 16 rows x 16 float4)
    {
        const int r = tid >> 4, c4 = (tid & 15) << 2;
        float4 val = (r < nq) ? *(const float4*)(q + (size_t)(qt + r) * D_DIM + h * DH + c4)
                              : make_float4(0.f, 0.f, 0.f, 0.f);
        *(float4*)&Qs[r][c4] = val;
    }
    // zero sc tail [257..320) so the unguarded unrolled phase-3 reads zeros
    {
        const int r = tid >> 4, cb = tid & 15;           // 16 rows x 16 threads
        for (int c = 257 + cb * 4; c < 321; c += 64) {
#pragma unroll
            for (int u = 0; u < 4; u++) if (c + u < 321) sc[r][c + u] = 0.f;
        }
    }

    const int qrow = tid & 15, jg = tid >> 4;

    // phase 1: scores — each thread computes 4 consecutive j (Q reused)
    for (int j0 = 0; j0 < S_TOK; j0 += 64) {
        const int jn = min(64, S_TOK - j0);
        __syncthreads();
#pragma unroll
        for (int i = 0; i < 4; i++) {
            const int idx = tid + i * 256;
            const int r = idx >> 4, c4 = (idx & 15) << 2;
            float4 val = (r < jn) ? *(const float4*)(k + (size_t)(j0 + r) * D_DIM + h * DH + c4)
                                  : make_float4(0.f, 0.f, 0.f, 0.f);
            *(float4*)&T[r][c4] = val;
        }
        __syncthreads();
        {
            const int jb = jg * 4;
            float s0 = 0.f, s1 = 0.f, s2 = 0.f, s3 = 0.f;
            const float4* qr4 = (const float4*)Qs[qrow];
#pragma unroll
            for (int t = 0; t < 16; t++) {
                const float4 a = qr4[t];
                const float4 k0v = *(const float4*)&T[jb + 0][t * 4];
                const float4 k1v = *(const float4*)&T[jb + 1][t * 4];
                const float4 k2v = *(const float4*)&T[jb + 2][t * 4];
                const float4 k3v = *(const float4*)&T[jb + 3][t * 4];
                s0 += a.x * k0v.x + a.y * k0v.y + a.z * k0v.z + a.w * k0v.w;
                s1 += a.x * k1v.x + a.y * k1v.y + a.z * k1v.z + a.w * k1v.w;
                s2 += a.x * k2v.x + a.y * k2v.y + a.z * k2v.z + a.w * k2v.w;
                s3 += a.x * k3v.x + a.y * k3v.y + a.z * k3v.z + a.w * k3v.w;
            }
            if (jb + 0 < jn) sc[qrow][j0 + jb + 0] = s0 * 0.125f;
            if (jb + 1 < jn) sc[qrow][j0 + jb + 1] = s1 * 0.125f;
            if (jb + 2 < jn) sc[qrow][j0 + jb + 2] = s2 * 0.125f;
            if (jb + 3 < jn) sc[qrow][j0 + jb + 3] = s3 * 0.125f;
        }
    }
    __syncthreads();

    // phase 2: softmax (one warp -> 2 rows); only j < S_TOK touched
#pragma unroll
    for (int ri = 0; ri < 2; ri++) {
        const int r = warp * 2 + ri;
        if (r < nq) {
            float m = -1e30f;
            for (int j = lane; j < S_TOK; j += 32) m = fmaxf(m, sc[r][j]);
            m = warpMax(m);
            float ssum = 0.f;
            for (int j = lane; j < S_TOK; j += 32) {
                const float e = __expf(sc[r][j] - m);
                sc[r][j] = e;
                ssum += e;
            }
            ssum = warpSum(ssum);
            if (lane == 0) inv_s[r] = 1.0f / ssum;
        }
    }
    __syncthreads();

    // phase 3: attn @ V — 4x unrolled, two accumulator chains, no guards
    const int db = (tid >> 4) << 2;
    float4 accA = make_float4(0.f, 0.f, 0.f, 0.f);
    float4 accB = make_float4(0.f, 0.f, 0.f, 0.f);
    for (int j0 = 0; j0 < S_TOK; j0 += 64) {
        const int jn = min(64, S_TOK - j0);
        __syncthreads();
#pragma unroll
        for (int i = 0; i < 4; i++) {
            const int idx = tid + i * 256;
            const int r = idx >> 4, c4 = (idx & 15) << 2;
            float4 val = (r < jn) ? *(const float4*)(v + (size_t)(j0 + r) * D_DIM + h * DH + c4)
                                  : make_float4(0.f, 0.f, 0.f, 0.f);
            *(float4*)&T[r][c4] = val;
        }
        __syncthreads();
#pragma unroll 4
        for (int jj = 0; jj < 64; jj += 4) {
            const float w0 = sc[qrow][j0 + jj + 0];
            const float w1 = sc[qrow][j0 + jj + 1];
            const float w2 = sc[qrow][j0 + jj + 2];
            const float w3 = sc[qrow][j0 + jj + 3];
            const float4 v0 = *(const float4*)&T[jj + 0][db];
            const float4 v1 = *(const float4*)&T[jj + 1][db];
            const float4 v2 = *(const float4*)&T[jj + 2][db];
            const float4 v3 = *(const float4*)&T[jj + 3][db];
            accA.x += w0 * v0.x + w2 * v2.x;  accB.x += w1 * v1.x + w3 * v3.x;
            accA.y += w0 * v0.y + w2 * v2.y;  accB.y += w1 * v1.y + w3 * v3.y;
            accA.z += w0 * v0.z + w2 * v2.z;  accB.z += w1 * v1.z + w3 * v3.z;
            accA.w += w0 * v0.w + w2 * v2.w;  accB.w += w1 * v1.w + w3 * v3.w;
        }
    }
    if (qrow < nq) {
        const float iv = inv_s[qrow];
        float4 oo = {(accA.x + accB.x) * iv, (accA.y + accB.y) * iv,
                     (accA.z + accB.z) * iv, (accA.w + accB.w) * iv};
        *(float4*)(o + (size_t)(qt + qrow) * D_DIM + h * DH + db) = oo;
    }
}

// ---------------- matvec (embeddings / heads) -------------------------------
__global__ __launch_bounds__(256) void matvec_kernel(
    const float* __restrict__ W, const float* __restrict__ bias,
    const float* __restrict__ x, float* __restrict__ out,
    int N, int K, int act)
{
    __shared__ float xs[OBS_N];
    const int tid = threadIdx.x;
    for (int i = tid; i < K; i += 256) xs[i] = x[i];
    __syncthreads();
    const int warp = tid >> 5, lane = tid & 31;
    const int n = blockIdx.x * 8 + warp;
    if (n >= N) return;
    const float4* wr = reinterpret_cast<const float4*>(W + (size_t)n * K);
    const float4* x4 = reinterpret_cast<const float4*>(xs);
    float s = 0.f;
    const int K4 = K >> 2;
    for (int kb = lane; kb < K4; kb += 32) {
        const float4 w = wr[kb], xv = x4[kb];
        s += w.x * xv.x + w.y * xv.y + w.z * xv.z + w.w * xv.w;
    }
    s = warpSum(s);
    if (lane == 0) {
        s += bias[n];
        if (act == 1) s = fmaxf(s, 0.f);
        else if (act == 2) s = tanhf(s);
        out[n] = s;
    }
}

// ---------------- concept embedding (rows 1..256 of x) ---------------------
__global__ __launch_bounds__(256) void cemb_kernel(
    const float* __restrict__ concepts, const float* __restrict__ Wc,
    const float* __restrict__ bc, const float* __restrict__ Wage,
    const float* __restrict__ bage, float* __restrict__ x)
{
    const int i = blockIdx.x;
    const int tid = threadIdx.x;
    __shared__ float cv[CSZ];
    if (tid < CSZ) cv[tid] = concepts[i * CSZ + tid];
    __syncthreads();
    const float agef = (float)i / 256.0f;
    for (int d = tid; d < D_DIM; d += 256) {
        const float4* wr = reinterpret_cast<const float4*>(Wc + (size_t)d * CSZ);
        const float4* c4 = reinterpret_cast<const float4*>(cv);
        float s = 0.f;
#pragma unroll
        for (int t = 0; t < CSZ / 4; t++) {
            const float4 w = wr[t], c = c4[t];
            s += w.x * c.x + w.y * c.y + w.z * c.z + w.w * c.w;
        }
        s += bc[d] + Wage[(size_t)d * AGE_V + i] + agef * Wage[(size_t)d * AGE_V + (AGE_V - 1)] + bage[d];
        x[(size_t)(i + 1) * D_DIM + d] = s;
    }
}

// ---------------- host launch ----------------------------------------------
extern "C" void kernel_launch(void* const* d_in, const int* in_sizes, int n_in,
                              void* d_out, int out_size)
{
    const float* observation = (const float*)d_in[0];
    const float* concepts    = (const float*)d_in[1];
    const float* W_core = (const float*)d_in[2];
    const float* b_core = (const float*)d_in[3];
    const float* W_cemb = (const float*)d_in[4];
    const float* b_cemb = (const float*)d_in[5];
    const float* W_age  = (const float*)d_in[6];
    const float* b_age  = (const float*)d_in[7];
    const float* Wq = (const float*)d_in[8];
    const float* bq = (const float*)d_in[9];
    const float* Wk = (const float*)d_in[10];
    const float* bk = (const float*)d_in[11];
    const float* Wv = (const float*)d_in[12];
    const float* bv = (const float*)d_in[13];
    const float* Wo = (const float*)d_in[14];
    const float* bo = (const float*)d_in[15];
    const float* ln1_g = (const float*)d_in[16];
    const float* ln1_b = (const float*)d_in[17];
    const float* W1 = (const float*)d_in[18];
    const float* b1 = (const float*)d_in[19];
    const float* W2 = (const float*)d_in[20];
    const float* b2 = (const float*)d_in[21];
    const float* ln2_g = (const float*)d_in[22];
    const float* ln2_b = (const float*)d_in[23];
    const float* W_concept = (const float*)d_in[24];
    const float* b_concept = (const float*)d_in[25];
    const float* W_out = (const float*)d_in[26];
    const float* b_out = (const float*)d_in[27];

    float *x, *q, *k, *v, *ao, *ffn, *part;
    cudaGetSymbolAddress((void**)&x, g_x);
    cudaGetSymbolAddress((void**)&q, g_q);
    cudaGetSymbolAddress((void**)&k, g_k);
    cudaGetSymbolAddress((void**)&v, g_v);
    cudaGetSymbolAddress((void**)&ao, g_ao);
    cudaGetSymbolAddress((void**)&ffn, g_ffn);
    cudaGetSymbolAddress((void**)&part, g_part);

    const int M = S_TOK;
    const dim3 blk(256);
    const int MT = (M + 63) / 64;                 // 5 m-tiles
    const dim3 grid_qkv(D_DIM / 64, MT, 3);       // 240 blocks
    const dim3 grid_o(D_DIM / 64, MT, 2);         // split-K=2, 160 blocks
    const dim3 grid_w1(HID / 64, MT, 1);          // 320 blocks
    const dim3 grid_w2(D_DIM / 64, MT, 4);        // split-K=4, 320 blocks
    const dim3 grid_attn(HEADS, (S_TOK + QT - 1) / QT);   // 16 x 17

    // --- embeddings ---
    matvec_kernel<<<D_DIM / 8, 256>>>(W_core, b_core, observation, x, D_DIM, OBS_N, 0);
    cemb_kernel<<<NC, 256>>>(concepts, W_cemb, b_cemb, W_age, b_age, x);

    // --- transformer layers ---
    for (int l = 0; l < NLAYER; l++) {
        const size_t od  = (size_t)l * D_DIM * D_DIM;
        const size_t ob  = (size_t)l * D_DIM;
        const size_t o1w = (size_t)l * HID * D_DIM;
        const size_t o1b = (size_t)l * HID;

        gemm_qkv_kernel<<<grid_qkv, blk>>>(x, Wq + od, Wk + od, Wv + od,
                                           bq + ob, bk + ob, bv + ob,
                                           q, k, v, M, D_DIM, D_DIM);

        attn3_kernel<<<grid_attn, blk>>>(q, k, v, ao);

        gemm_splitk_kernel<<<grid_o, blk>>>(ao, Wo + od, part, M, D_DIM, D_DIM, D_DIM / 2);
        combine_ln_kernel<<<M, 256>>>(part, 2, bo + ob, x, ln1_g + ob, ln1_b + ob, x, M);

        gemm_direct_kernel<<<grid_w1, blk>>>(x, W1 + o1w, b1 + o1b, ffn, M, HID, D_DIM, 1);
        gemm_splitk_kernel<<<grid_w2, blk>>>(ffn, W2 + o1w, part, M, D_DIM, HID, HID / 4);
        combine_ln_kernel<<<M, 256>>>(part, 4, b2 + ob, x, ln2_g + ob, ln2_b + ob, x, M);
    }

    // --- heads (node 0) -> d_out = [output(512) | new_concept(128)] ---
    float* out = (float*)d_out;
    matvec_kernel<<<OUT_N / 8, 256>>>(W_out, b_out, x, out, OUT_N, D_DIM, 1);
    matvec_kernel<<<CSZ / 8, 256>>>(W_concept, b_concept, x, out + OUT_N, CSZ, D_DIM, 2);

    (void)in_sizes; (void)n_in; (void)out_size;
}

// round 7
// speedup vs baseline: 1.8979x; 1.0190x over previous
#include <cuda_runtime.h>
#include <math.h>
#include <stdint.h>

#define S_TOK 257
#define D_DIM 1024
#define HID 4096
#define NLAYER 12
#define NC 256
#define CSZ 128
#define AGE_V 258
#define OBS_N 2048
#define OUT_N 512
#define HEADS 16
#define DH 64

// ---------------- scratch (device globals; no allocation allowed) ----------
__device__ float g_x[S_TOK * D_DIM];
__device__ float g_q[S_TOK * D_DIM];
__device__ float g_k[S_TOK * D_DIM];
__device__ float g_v[S_TOK * D_DIM];
__device__ float g_ao[S_TOK * D_DIM];
__device__ float g_ffn[S_TOK * HID];
__device__ float g_part[4 * S_TOK * D_DIM];   // split-K partials (KS<=4)

// ---------------- helpers ---------------------------------------------------
__device__ __forceinline__ float warpMax(float v) {
#pragma unroll
    for (int o = 16; o; o >>= 1) v = fmaxf(v, __shfl_xor_sync(0xffffffffu, v, o));
    return v;
}
__device__ __forceinline__ float warpSum(float v) {
#pragma unroll
    for (int o = 16; o; o >>= 1) v += __shfl_xor_sync(0xffffffffu, v, o);
    return v;
}
__device__ __forceinline__ uint32_t f2tf(float f) {
    uint32_t u;
    asm("cvt.rna.tf32.f32 %0, %1;" : "=r"(u) : "f"(f));
    return u;
}
__device__ __forceinline__ void mma1688(float (&d)[4], const uint32_t (&a)[4], const uint32_t (&b)[2]) {
    asm volatile(
        "mma.sync.aligned.m16n8k8.row.col.f32.tf32.tf32.f32 "
        "{%0,%1,%2,%3}, {%4,%5,%6,%7}, {%8,%9}, {%0,%1,%2,%3};\n"
        : "+f"(d[0]), "+f"(d[1]), "+f"(d[2]), "+f"(d[3])
        : "r"(a[0]), "r"(a[1]), "r"(a[2]), "r"(a[3]), "r"(b[0]), "r"(b[1]));
}

// ============================================================================
// tf32 GEMM core: C[M,N] = A[M,K] @ B[N,K]^T. Block 64x64, BK=32, 256 threads.
// Used ONLY for full tiles (rows bm..bm+63 all valid).
// ============================================================================
__device__ __forceinline__ void tf32_core(
    const float* __restrict__ A, const float* __restrict__ B,
    int K, int bm, int bn, int kbeg, int ktiles,
    float (&acc)[2][2][4], uint32_t (*As)[36], uint32_t (*Bs)[36])
{
    const int tid = threadIdx.x;
    const int lane = tid & 31, wid = tid >> 5;
    const int wm = wid & 1, wn = wid >> 1;
    const int fr = lane >> 2, fc = lane & 3;

    int arow[2], akq[2];
    const float* aptr[2];
    const float* bptr[2];
#pragma unroll
    for (int i = 0; i < 2; i++) {
        const int idx = tid + i * 256;
        const int row = idx >> 3, kq = (idx & 7) << 2;
        arow[i] = row; akq[i] = kq;
        aptr[i] = A + (size_t)(bm + row) * K + kbeg + kq;
        bptr[i] = B + (size_t)(bn + row) * K + kbeg + kq;
    }

    float4 pa[2], pb[2];
#pragma unroll
    for (int i = 0; i < 2; i++) {
        pa[i] = *(const float4*)(aptr[i]);
        pb[i] = *(const float4*)(bptr[i]);
    }
#pragma unroll
    for (int i = 0; i < 2; i++) {
        *(uint4*)&As[arow[i]][akq[i]] = make_uint4(f2tf(pa[i].x), f2tf(pa[i].y), f2tf(pa[i].z), f2tf(pa[i].w));
        *(uint4*)&Bs[arow[i]][akq[i]] = make_uint4(f2tf(pb[i].x), f2tf(pb[i].y), f2tf(pb[i].z), f2tf(pb[i].w));
    }
    __syncthreads();

    for (int kt = 0; kt < ktiles; kt++) {
        const bool has_next = (kt + 1 < ktiles);
        if (has_next) {
            const int off = (kt + 1) * 32;
#pragma unroll
            for (int i = 0; i < 2; i++) {
                pa[i] = *(const float4*)(aptr[i] + off);
                pb[i] = *(const float4*)(bptr[i] + off);
            }
        }
#pragma unroll
        for (int k0 = 0; k0 < 32; k0 += 8) {
            uint32_t af[2][4], bf[2][2];
#pragma unroll
            for (int mi = 0; mi < 2; mi++) {
                const int r = wm * 32 + mi * 16 + fr;
                af[mi][0] = As[r][k0 + fc];
                af[mi][1] = As[r + 8][k0 + fc];
                af[mi][2] = As[r][k0 + fc + 4];
                af[mi][3] = As[r + 8][k0 + fc + 4];
            }
#pragma unroll
            for (int ni = 0; ni < 2; ni++) {
                const int c = wn * 16 + ni * 8 + fr;
                bf[ni][0] = Bs[c][k0 + fc];
                bf[ni][1] = Bs[c][k0 + fc + 4];
            }
#pragma unroll
            for (int mi = 0; mi < 2; mi++)
#pragma unroll
                for (int ni = 0; ni < 2; ni++)
                    mma1688(acc[mi][ni], af[mi], bf[ni]);
        }
        if (has_next) {
            __syncthreads();
#pragma unroll
            for (int i = 0; i < 2; i++) {
                *(uint4*)&As[arow[i]][akq[i]] = make_uint4(f2tf(pa[i].x), f2tf(pa[i].y), f2tf(pa[i].z), f2tf(pa[i].w));
                *(uint4*)&Bs[arow[i]][akq[i]] = make_uint4(f2tf(pb[i].x), f2tf(pb[i].y), f2tf(pb[i].z), f2tf(pb[i].w));
            }
            __syncthreads();
        }
    }
}

// ---- slim path: compute single row (row 256) as fp32 matvec -----------------
// xs: smem scratch (>= klen floats). Each of 8 warps handles 8 of 64 cols.
__device__ __forceinline__ void slim_row(
    const float* __restrict__ Arow,   // A + 256*K + kbeg
    const float* __restrict__ B,      // weight base
    int K, int bn, int kbeg, int klen,
    float* xs, float* outvals /*8 per warp via lane0*/, int* outcols)
{
    const int tid = threadIdx.x;
    const int wid = tid >> 5, lane = tid & 31;
    const int k4 = klen >> 2;
    for (int i = tid; i < k4; i += 256)
        ((float4*)xs)[i] = ((const float4*)Arow)[i];
    __syncthreads();
#pragma unroll
    for (int cc = 0; cc < 8; cc++) {
        const int col = bn + wid * 8 + cc;
        const float4* wr = (const float4*)(B + (size_t)col * K + kbeg);
        float s = 0.f;
        for (int kb = lane; kb < k4; kb += 32) {
            const float4 w = wr[kb], xv = ((const float4*)xs)[kb];
            s += w.x * xv.x + w.y * xv.y + w.z * xv.z + w.w * xv.w;
        }
        s = warpSum(s);
        outvals[cc] = s;
        outcols[cc] = col;
    }
}

// ---- fused QKV ---------------------------------------------------------------
__global__ __launch_bounds__(256) void gemm_qkv_kernel(
    const float* __restrict__ A,
    const float* __restrict__ Wq_, const float* __restrict__ Wk_, const float* __restrict__ Wv_,
    const float* __restrict__ bq_, const float* __restrict__ bk_, const float* __restrict__ bv_,
    float* __restrict__ Q, float* __restrict__ Ko, float* __restrict__ V,
    int M, int N, int K)
{
    __shared__ uint32_t As[64][36];
    __shared__ uint32_t Bs[64][36];
    const int z = blockIdx.z;
    const float* B    = (z == 0) ? Wq_ : (z == 1) ? Wk_ : Wv_;
    const float* bias = (z == 0) ? bq_ : (z == 1) ? bk_ : bv_;
    float* C          = (z == 0) ? Q   : (z == 1) ? Ko  : V;
    const int bn = blockIdx.x * 64;

    if (blockIdx.y == 4) {   // slim: row 256 only
        float vals[8]; int cols[8];
        slim_row(A + (size_t)256 * K, B, K, bn, 0, K, (float*)As, vals, cols);
        const int lane = threadIdx.x & 31;
        if (lane == 0) {
#pragma unroll
            for (int cc = 0; cc < 8; cc++)
                C[(size_t)256 * N + cols[cc]] = vals[cc] + bias[cols[cc]];
        }
        return;
    }

    const int bm = blockIdx.y * 64;
    float acc[2][2][4] = {};
    tf32_core(A, B, K, bm, bn, 0, K / 32, acc, As, Bs);

    const int lane = threadIdx.x & 31, wid = threadIdx.x >> 5;
    const int wm = wid & 1, wn = wid >> 1;
    const int fr = lane >> 2, fc = lane & 3;
#pragma unroll
    for (int mi = 0; mi < 2; mi++)
#pragma unroll
        for (int ni = 0; ni < 2; ni++) {
            const int r = bm + wm * 32 + mi * 16 + fr;
            const int c = bn + wn * 16 + ni * 8 + fc * 2;
            const float bx = bias[c], by = bias[c + 1];
            float2 o0 = {acc[mi][ni][0] + bx, acc[mi][ni][1] + by};
            float2 o1 = {acc[mi][ni][2] + bx, acc[mi][ni][3] + by};
            *(float2*)(C + (size_t)r * N + c) = o0;
            *(float2*)(C + (size_t)(r + 8) * N + c) = o1;
        }
}

// ---- direct GEMM with bias (+relu) -------------------------------------------
__global__ __launch_bounds__(256) void gemm_direct_kernel(
    const float* __restrict__ A, const float* __restrict__ B,
    const float* __restrict__ bias, float* __restrict__ C,
    int M, int N, int K, int relu_flag)
{
    __shared__ uint32_t As[64][36];
    __shared__ uint32_t Bs[64][36];
    const int bn = blockIdx.x * 64;

    if (blockIdx.y == 4) {
        float vals[8]; int cols[8];
        slim_row(A + (size_t)256 * K, B, K, bn, 0, K, (float*)As, vals, cols);
        const int lane = threadIdx.x & 31;
        if (lane == 0) {
#pragma unroll
            for (int cc = 0; cc < 8; cc++) {
                float s = vals[cc] + bias[cols[cc]];
                if (relu_flag) s = fmaxf(s, 0.f);
                C[(size_t)256 * N + cols[cc]] = s;
            }
        }
        return;
    }

    const int bm = blockIdx.y * 64;
    float acc[2][2][4] = {};
    tf32_core(A, B, K, bm, bn, 0, K / 32, acc, As, Bs);

    const int lane = threadIdx.x & 31, wid = threadIdx.x >> 5;
    const int wm = wid & 1, wn = wid >> 1;
    const int fr = lane >> 2, fc = lane & 3;
#pragma unroll
    for (int mi = 0; mi < 2; mi++)
#pragma unroll
        for (int ni = 0; ni < 2; ni++) {
            const int r = bm + wm * 32 + mi * 16 + fr;
            const int c = bn + wn * 16 + ni * 8 + fc * 2;
            const float bx = bias[c], by = bias[c + 1];
            float2 o0 = {acc[mi][ni][0] + bx, acc[mi][ni][1] + by};
            float2 o1 = {acc[mi][ni][2] + bx, acc[mi][ni][3] + by};
            if (relu_flag) {
                o0.x = fmaxf(o0.x, 0.f); o0.y = fmaxf(o0.y, 0.f);
                o1.x = fmaxf(o1.x, 0.f); o1.y = fmaxf(o1.y, 0.f);
            }
            *(float2*)(C + (size_t)r * N + c) = o0;
            *(float2*)(C + (size_t)(r + 8) * N + c) = o1;
        }
}

// ---- split-K GEMM (raw partials) ---------------------------------------------
__global__ __launch_bounds__(256) void gemm_splitk_kernel(
    const float* __restrict__ A, const float* __restrict__ B,
    float* __restrict__ part, int M, int N, int K, int klen)
{
    __shared__ uint32_t As[64][36];
    __shared__ uint32_t Bs[64][36];
    const int bn = blockIdx.x * 64;
    const int z = blockIdx.z;
    float* C = part + (size_t)z * M * N;

    if (blockIdx.y == 4) {
        float vals[8]; int cols[8];
        slim_row(A + (size_t)256 * K + z * klen, B, K, bn, z * klen, klen, (float*)As, vals, cols);
        const int lane = threadIdx.x & 31;
        if (lane == 0) {
#pragma unroll
            for (int cc = 0; cc < 8; cc++)
                C[(size_t)256 * N + cols[cc]] = vals[cc];
        }
        return;
    }

    const int bm = blockIdx.y * 64;
    float acc[2][2][4] = {};
    tf32_core(A, B, K, bm, bn, z * klen, klen / 32, acc, As, Bs);

    const int lane = threadIdx.x & 31, wid = threadIdx.x >> 5;
    const int wm = wid & 1, wn = wid >> 1;
    const int fr = lane >> 2, fc = lane & 3;
#pragma unroll
    for (int mi = 0; mi < 2; mi++)
#pragma unroll
        for (int ni = 0; ni < 2; ni++) {
            const int r = bm + wm * 32 + mi * 16 + fr;
            const int c = bn + wn * 16 + ni * 8 + fc * 2;
            float2 o0 = {acc[mi][ni][0], acc[mi][ni][1]};
            float2 o1 = {acc[mi][ni][2], acc[mi][ni][3]};
            *(float2*)(C + (size_t)r * N + c) = o0;
            *(float2*)(C + (size_t)(r + 8) * N + c) = o1;
        }
}

// ---- fused combine(split-K) + bias + residual + LayerNorm --------------------
__global__ __launch_bounds__(256) void combine_ln_kernel(
    const float* __restrict__ part, int KS,
    const float* __restrict__ bias, const float* __restrict__ res,
    const float* __restrict__ g, const float* __restrict__ b,
    float* __restrict__ out, int M)
{
    const int row = blockIdx.x;
    const int tid = threadIdx.x;
    const int lane = tid & 31, warp = tid >> 5;
    __shared__ float rs[8], rs2[8];
    __shared__ float smv[2];

    float4 s = ((const float4*)(part + (size_t)row * D_DIM))[tid];
    for (int z = 1; z < KS; z++) {
        const float4 t = ((const float4*)(part + ((size_t)z * M + row) * D_DIM))[tid];
        s.x += t.x; s.y += t.y; s.z += t.z; s.w += t.w;
    }
    const float4 b4 = ((const float4*)bias)[tid];
    s.x += b4.x; s.y += b4.y; s.z += b4.z; s.w += b4.w;
    const float4 r4 = ((const float4*)(res + (size_t)row * D_DIM))[tid];
    s.x += r4.x; s.y += r4.y; s.z += r4.z; s.w += r4.w;

    float sum = s.x + s.y + s.z + s.w;
    float sq = s.x * s.x + s.y * s.y + s.z * s.z + s.w * s.w;
    sum = warpSum(sum); sq = warpSum(sq);
    if (lane == 0) { rs[warp] = sum; rs2[warp] = sq; }
    __syncthreads();
    if (warp == 0) {
        float t = (lane < 8) ? rs[lane] : 0.f;
        float t2 = (lane < 8) ? rs2[lane] : 0.f;
        t = warpSum(t); t2 = warpSum(t2);
        if (lane == 0) {
            const float mean = t * (1.0f / D_DIM);
            const float var = t2 * (1.0f / D_DIM) - mean * mean;
            smv[0] = mean;
            smv[1] = rsqrtf(var + 1e-5f);
        }
    }
    __syncthreads();
    const float mean = smv[0], inv = smv[1];
    const float4 g4 = ((const float4*)g)[tid];
    const float4 be4 = ((const float4*)b)[tid];
    float4 o;
    o.x = (s.x - mean) * inv * g4.x + be4.x;
    o.y = (s.y - mean) * inv * g4.y + be4.y;
    o.z = (s.z - mean) * inv * g4.z + be4.z;
    o.w = (s.w - mean) * inv * g4.w + be4.w;
    ((float4*)(out + (size_t)row * D_DIM))[tid] = o;
}

// ---------------- attention: block per (head, 8-query tile), 128 threads ----
// 528 blocks -> ~3.6 blocks/SM. sc padded: cols [257..320] zeroed so phase-3
// runs unguarded 4x-unrolled. Stride 325 (mod 32 = 5) -> conflict-free.
#define QT 8
#define SC_W 325
__global__ __launch_bounds__(128) void attn4_kernel(
    const float* __restrict__ q, const float* __restrict__ k,
    const float* __restrict__ v, float* __restrict__ o)
{
    const int h = blockIdx.x;
    const int qt = blockIdx.y * QT;
    const int tid = threadIdx.x, lane = tid & 31, warp = tid >> 5;

    __shared__ float Qs[QT][68];
    __shared__ float T[64][68];
    __shared__ float sc[QT][SC_W];
    __shared__ float inv_s[QT];

    const int nq = min(QT, S_TOK - qt);

    // load Q tile (128 threads = 8 rows x 16 float4)
    {
        const int r = tid >> 4, c4 = (tid & 15) << 2;
        float4 val = (r < nq) ? *(const float4*)(q + (size_t)(qt + r) * D_DIM + h * DH + c4)
                              : make_float4(0.f, 0.f, 0.f, 0.f);
        *(float4*)&Qs[r][c4] = val;
    }
    // zero sc tail [257..320]: 8 rows x 64 cols, 16 threads/row x 4 cols
    {
        const int r = tid >> 4;
        const int c = 257 + (tid & 15) * 4;
#pragma unroll
        for (int u = 0; u < 4; u++) sc[r][c + u] = 0.f;
    }

    const int qrow = tid & 7, jg = tid >> 3;   // 16 j-groups

    // phase 1: scores — each thread computes 4 consecutive j (Q reused)
    for (int j0 = 0; j0 < S_TOK; j0 += 64) {
        const int jn = min(64, S_TOK - j0);
        __syncthreads();
#pragma unroll
        for (int i = 0; i < 8; i++) {
            const int idx = tid + i * 128;
            const int r = idx >> 4, c4 = (idx & 15) << 2;
            float4 val = (r < jn) ? *(const float4*)(k + (size_t)(j0 + r) * D_DIM + h * DH + c4)
                                  : make_float4(0.f, 0.f, 0.f, 0.f);
            *(float4*)&T[r][c4] = val;
        }
        __syncthreads();
        {
            const int jb = jg * 4;
            float s0 = 0.f, s1 = 0.f, s2 = 0.f, s3 = 0.f;
            const float4* qr4 = (const float4*)Qs[qrow];
#pragma unroll
            for (int t = 0; t < 16; t++) {
                const float4 a = qr4[t];
                const float4 k0v = *(const float4*)&T[jb + 0][t * 4];
                const float4 k1v = *(const float4*)&T[jb + 1][t * 4];
                const float4 k2v = *(const float4*)&T[jb + 2][t * 4];
                const float4 k3v = *(const float4*)&T[jb + 3][t * 4];
                s0 += a.x * k0v.x + a.y * k0v.y + a.z * k0v.z + a.w * k0v.w;
                s1 += a.x * k1v.x + a.y * k1v.y + a.z * k1v.z + a.w * k1v.w;
                s2 += a.x * k2v.x + a.y * k2v.y + a.z * k2v.z + a.w * k2v.w;
                s3 += a.x * k3v.x + a.y * k3v.y + a.z * k3v.z + a.w * k3v.w;
            }
            if (jb + 0 < jn) sc[qrow][j0 + jb + 0] = s0 * 0.125f;
            if (jb + 1 < jn) sc[qrow][j0 + jb + 1] = s1 * 0.125f;
            if (jb + 2 < jn) sc[qrow][j0 + jb + 2] = s2 * 0.125f;
            if (jb + 3 < jn) sc[qrow][j0 + jb + 3] = s3 * 0.125f;
        }
    }
    __syncthreads();

    // phase 2: softmax (one warp -> 2 rows)
#pragma unroll
    for (int ri = 0; ri < 2; ri++) {
        const int r = warp * 2 + ri;
        if (r < nq) {
            float m = -1e30f;
            for (int j = lane; j < S_TOK; j += 32) m = fmaxf(m, sc[r][j]);
            m = warpMax(m);
            float ssum = 0.f;
            for (int j = lane; j < S_TOK; j += 32) {
                const float e = __expf(sc[r][j] - m);
                sc[r][j] = e;
                ssum += e;
            }
            ssum = warpSum(ssum);
            if (lane == 0) inv_s[r] = 1.0f / ssum;
        }
    }
    __syncthreads();

    // phase 3: attn @ V — 4x unrolled, two accumulator chains, no guards
    const int db = (tid >> 3) << 2;    // 16 dim-groups x 4
    float4 accA = make_float4(0.f, 0.f, 0.f, 0.f);
    float4 accB = make_float4(0.f, 0.f, 0.f, 0.f);
    for (int j0 = 0; j0 < S_TOK; j0 += 64) {
        const int jn = min(64, S_TOK - j0);
        __syncthreads();
#pragma unroll
        for (int i = 0; i < 8; i++) {
            const int idx = tid + i * 128;
            const int r = idx >> 4, c4 = (idx & 15) << 2;
            float4 val = (r < jn) ? *(const float4*)(v + (size_t)(j0 + r) * D_DIM + h * DH + c4)
                                  : make_float4(0.f, 0.f, 0.f, 0.f);
            *(float4*)&T[r][c4] = val;
        }
        __syncthreads();
#pragma unroll 4
        for (int jj = 0; jj < 64; jj += 4) {
            const float w0 = sc[qrow][j0 + jj + 0];
            const float w1 = sc[qrow][j0 + jj + 1];
            const float w2 = sc[qrow][j0 + jj + 2];
            const float w3 = sc[qrow][j0 + jj + 3];
            const float4 v0 = *(const float4*)&T[jj + 0][db];
            const float4 v1 = *(const float4*)&T[jj + 1][db];
            const float4 v2 = *(const float4*)&T[jj + 2][db];
            const float4 v3 = *(const float4*)&T[jj + 3][db];
            accA.x += w0 * v0.x + w2 * v2.x;  accB.x += w1 * v1.x + w3 * v3.x;
            accA.y += w0 * v0.y + w2 * v2.y;  accB.y += w1 * v1.y + w3 * v3.y;
            accA.z += w0 * v0.z + w2 * v2.z;  accB.z += w1 * v1.z + w3 * v3.z;
            accA.w += w0 * v0.w + w2 * v2.w;  accB.w += w1 * v1.w + w3 * v3.w;
        }
    }
    if (qrow < nq) {
        const float iv = inv_s[qrow];
        float4 oo = {(accA.x + accB.x) * iv, (accA.y + accB.y) * iv,
                     (accA.z + accB.z) * iv, (accA.w + accB.w) * iv};
        *(float4*)(o + (size_t)(qt + qrow) * D_DIM + h * DH + db) = oo;
    }
}

// ---------------- matvec (embeddings / heads) -------------------------------
__global__ __launch_bounds__(256) void matvec_kernel(
    const float* __restrict__ W, const float* __restrict__ bias,
    const float* __restrict__ x, float* __restrict__ out,
    int N, int K, int act)
{
    __shared__ float xs[OBS_N];
    const int tid = threadIdx.x;
    for (int i = tid; i < K; i += 256) xs[i] = x[i];
    __syncthreads();
    const int warp = tid >> 5, lane = tid & 31;
    const int n = blockIdx.x * 8 + warp;
    if (n >= N) return;
    const float4* wr = reinterpret_cast<const float4*>(W + (size_t)n * K);
    const float4* x4 = reinterpret_cast<const float4*>(xs);
    float s = 0.f;
    const int K4 = K >> 2;
    for (int kb = lane; kb < K4; kb += 32) {
        const float4 w = wr[kb], xv = x4[kb];
        s += w.x * xv.x + w.y * xv.y + w.z * xv.z + w.w * xv.w;
    }
    s = warpSum(s);
    if (lane == 0) {
        s += bias[n];
        if (act == 1) s = fmaxf(s, 0.f);
        else if (act == 2) s = tanhf(s);
        out[n] = s;
    }
}

// ---------------- concept embedding (rows 1..256 of x) ---------------------
__global__ __launch_bounds__(256) void cemb_kernel(
    const float* __restrict__ concepts, const float* __restrict__ Wc,
    const float* __restrict__ bc, const float* __restrict__ Wage,
    const float* __restrict__ bage, float* __restrict__ x)
{
    const int i = blockIdx.x;
    const int tid = threadIdx.x;
    __shared__ float cv[CSZ];
    if (tid < CSZ) cv[tid] = concepts[i * CSZ + tid];
    __syncthreads();
    const float agef = (float)i / 256.0f;
    for (int d = tid; d < D_DIM; d += 256) {
        const float4* wr = reinterpret_cast<const float4*>(Wc + (size_t)d * CSZ);
        const float4* c4 = reinterpret_cast<const float4*>(cv);
        float s = 0.f;
#pragma unroll
        for (int t = 0; t < CSZ / 4; t++) {
            const float4 w = wr[t], c = c4[t];
            s += w.x * c.x + w.y * c.y + w.z * c.z + w.w * c.w;
        }
        s += bc[d] + Wage[(size_t)d * AGE_V + i] + agef * Wage[(size_t)d * AGE_V + (AGE_V - 1)] + bage[d];
        x[(size_t)(i + 1) * D_DIM + d] = s;
    }
}

// ---------------- host launch ----------------------------------------------
extern "C" void kernel_launch(void* const* d_in, const int* in_sizes, int n_in,
                              void* d_out, int out_size)
{
    const float* observation = (const float*)d_in[0];
    const float* concepts    = (const float*)d_in[1];
    const float* W_core = (const float*)d_in[2];
    const float* b_core = (const float*)d_in[3];
    const float* W_cemb = (const float*)d_in[4];
    const float* b_cemb = (const float*)d_in[5];
    const float* W_age  = (const float*)d_in[6];
    const float* b_age  = (const float*)d_in[7];
    const float* Wq = (const float*)d_in[8];
    const float* bq = (const float*)d_in[9];
    const float* Wk = (const float*)d_in[10];
    const float* bk = (const float*)d_in[11];
    const float* Wv = (const float*)d_in[12];
    const float* bv = (const float*)d_in[13];
    const float* Wo = (const float*)d_in[14];
    const float* bo = (const float*)d_in[15];
    const float* ln1_g = (const float*)d_in[16];
    const float* ln1_b = (const float*)d_in[17];
    const float* W1 = (const float*)d_in[18];
    const float* b1 = (const float*)d_in[19];
    const float* W2 = (const float*)d_in[20];
    const float* b2 = (const float*)d_in[21];
    const float* ln2_g = (const float*)d_in[22];
    const float* ln2_b = (const float*)d_in[23];
    const float* W_concept = (const float*)d_in[24];
    const float* b_concept = (const float*)d_in[25];
    const float* W_out = (const float*)d_in[26];
    const float* b_out = (const float*)d_in[27];

    float *x, *q, *k, *v, *ao, *ffn, *part;
    cudaGetSymbolAddress((void**)&x, g_x);
    cudaGetSymbolAddress((void**)&q, g_q);
    cudaGetSymbolAddress((void**)&k, g_k);
    cudaGetSymbolAddress((void**)&v, g_v);
    cudaGetSymbolAddress((void**)&ao, g_ao);
    cudaGetSymbolAddress((void**)&ffn, g_ffn);
    cudaGetSymbolAddress((void**)&part, g_part);

    const int M = S_TOK;
    const dim3 blk(256);
    // y = 5: tiles 0..3 full (rows 0..255), tile 4 = slim path (row 256)
    const dim3 grid_qkv(D_DIM / 64, 5, 3);
    const dim3 grid_o(D_DIM / 64, 5, 2);          // split-K=2
    const dim3 grid_w1(HID / 64, 5, 1);
    const dim3 grid_w2(D_DIM / 64, 5, 4);         // split-K=4
    const dim3 grid_attn(HEADS, (S_TOK + QT - 1) / QT);   // 16 x 33 = 528

    // --- embeddings ---
    matvec_kernel<<<D_DIM / 8, 256>>>(W_core, b_core, observation, x, D_DIM, OBS_N, 0);
    cemb_kernel<<<NC, 256>>>(concepts, W_cemb, b_cemb, W_age, b_age, x);

    // --- transformer layers ---
    for (int l = 0; l < NLAYER; l++) {
        const size_t od  = (size_t)l * D_DIM * D_DIM;
        const size_t ob  = (size_t)l * D_DIM;
        const size_t o1w = (size_t)l * HID * D_DIM;
        const size_t o1b = (size_t)l * HID;

        gemm_qkv_kernel<<<grid_qkv, blk>>>(x, Wq + od, Wk + od, Wv + od,
                                           bq + ob, bk + ob, bv + ob,
                                           q, k, v, M, D_DIM, D_DIM);

        attn4_kernel<<<grid_attn, 128>>>(q, k, v, ao);

        gemm_splitk_kernel<<<grid_o, blk>>>(ao, Wo + od, part, M, D_DIM, D_DIM, D_DIM / 2);
        combine_ln_kernel<<<M, 256>>>(part, 2, bo + ob, x, ln1_g + ob, ln1_b + ob, x, M);

        gemm_direct_kernel<<<grid_w1, blk>>>(x, W1 + o1w, b1 + o1b, ffn, M, HID, D_DIM, 1);
        gemm_splitk_kernel<<<grid_w2, blk>>>(ffn, W2 + o1w, part, M, D_DIM, HID, HID / 4);
        combine_ln_kernel<<<M, 256>>>(part, 4, b2 + ob, x, ln2_g + ob, ln2_b + ob, x, M);
    }

    // --- heads (node 0) -> d_out = [output(512) | new_concept(128)] ---
    float* out = (float*)d_out;
    matvec_kernel<<<OUT_N / 8, 256>>>(W_out, b_out, x, out, OUT_N, D_DIM, 1);
    matvec_kernel<<<CSZ / 8, 256>>>(W_concept, b_concept, x, out + OUT_N, CSZ, D_DIM, 2);

    (void)in_sizes; (void)n_in; (void)out_size;
}

// round 9
// speedup vs baseline: 2.4206x; 1.2754x over previous
#include <cuda_runtime.h>
#include <math.h>
#include <stdint.h>

#define S_TOK 257
#define D_DIM 1024
#define HID 4096
#define NLAYER 12
#define NC 256
#define CSZ 128
#define AGE_V 258
#define OBS_N 2048
#define OUT_N 512
#define HEADS 16
#define DH 64

// ---------------- scratch (device globals; no allocation allowed) ----------
__device__ float g_x[S_TOK * D_DIM];
__device__ float g_q[S_TOK * D_DIM];
__device__ float g_k[S_TOK * D_DIM];
__device__ float g_v[S_TOK * D_DIM];
__device__ float g_ao[S_TOK * D_DIM];
__device__ float g_ffn[S_TOK * HID];
__device__ float g_part[4 * S_TOK * D_DIM];   // split-K partials (KS<=4)

// ---------------- helpers ---------------------------------------------------
__device__ __forceinline__ float warpMax(float v) {
#pragma unroll
    for (int o = 16; o; o >>= 1) v = fmaxf(v, __shfl_xor_sync(0xffffffffu, v, o));
    return v;
}
__device__ __forceinline__ float warpSum(float v) {
#pragma unroll
    for (int o = 16; o; o >>= 1) v += __shfl_xor_sync(0xffffffffu, v, o);
    return v;
}
// pack two floats into half2: lo = a, hi = b
__device__ __forceinline__ uint32_t pkh2(float a, float b) {
    uint32_t r;
    asm("cvt.rn.f16x2.f32 %0, %1, %2;" : "=r"(r) : "f"(b), "f"(a));
    return r;
}
__device__ __forceinline__ void mma16816(float (&d)[4], const uint32_t (&a)[4], const uint32_t (&b)[2]) {
    asm volatile(
        "mma.sync.aligned.m16n8k16.row.col.f32.f16.f16.f32 "
        "{%0,%1,%2,%3}, {%4,%5,%6,%7}, {%8,%9}, {%0,%1,%2,%3};\n"
        : "+f"(d[0]), "+f"(d[1]), "+f"(d[2]), "+f"(d[3])
        : "r"(a[0]), "r"(a[1]), "r"(a[2]), "r"(a[3]), "r"(b[0]), "r"(b[1]));
}

// ============================================================================
// fp16 GEMM core: C[M,N] = A[M,K] @ B[N,K]^T. Block 64x64, BK=32, 256 threads
// (8 warps 2x4, warp tile 32x16 via 2x2 m16n8k16 -> 2 k-steps per 32-K tile).
// Smem: u32 half2 rows, 16 data u32 per row, stride 20 (conflict-free frags).
// Coalesced float4 global loads, fp16 convert at STS, register prefetch.
// ============================================================================
__device__ __forceinline__ void f16_core(
    const float* __restrict__ A, const float* __restrict__ B,
    int K, int bm, int bn, int kbeg, int ktiles,
    float (&acc)[2][2][4], uint32_t (*As)[20], uint32_t (*Bs)[20])
{
    const int tid = threadIdx.x;
    const int lane = tid & 31, wid = tid >> 5;
    const int wm = wid & 1, wn = wid >> 1;
    const int fr = lane >> 2, fc = lane & 3;

    int arow[2], ac2[2];
    const float* aptr[2];
    const float* bptr[2];
#pragma unroll
    for (int i = 0; i < 2; i++) {
        const int idx = tid + i * 256;
        const int row = idx >> 3, kq = (idx & 7) << 2;
        arow[i] = row; ac2[i] = (idx & 7) * 2;
        aptr[i] = A + (size_t)(bm + row) * K + kbeg + kq;
        bptr[i] = B + (size_t)(bn + row) * K + kbeg + kq;
    }

    float4 pa[2], pb[2];
#pragma unroll
    for (int i = 0; i < 2; i++) {
        pa[i] = *(const float4*)(aptr[i]);
        pb[i] = *(const float4*)(bptr[i]);
    }
#pragma unroll
    for (int i = 0; i < 2; i++) {
        *(uint2*)&As[arow[i]][ac2[i]] = make_uint2(pkh2(pa[i].x, pa[i].y), pkh2(pa[i].z, pa[i].w));
        *(uint2*)&Bs[arow[i]][ac2[i]] = make_uint2(pkh2(pb[i].x, pb[i].y), pkh2(pb[i].z, pb[i].w));
    }
    __syncthreads();

    for (int kt = 0; kt < ktiles; kt++) {
        const bool has_next = (kt + 1 < ktiles);
        if (has_next) {
            const int off = (kt + 1) * 32;
#pragma unroll
            for (int i = 0; i < 2; i++) {
                pa[i] = *(const float4*)(aptr[i] + off);
                pb[i] = *(const float4*)(bptr[i] + off);
            }
        }
#pragma unroll
        for (int k0 = 0; k0 < 16; k0 += 8) {     // 2 k-steps (k16 each)
            uint32_t af[2][4], bf[2][2];
#pragma unroll
            for (int mi = 0; mi < 2; mi++) {
                const int r = wm * 32 + mi * 16 + fr;
                af[mi][0] = As[r][k0 + fc];
                af[mi][1] = As[r + 8][k0 + fc];
                af[mi][2] = As[r][k0 + fc + 4];
                af[mi][3] = As[r + 8][k0 + fc + 4];
            }
#pragma unroll
            for (int ni = 0; ni < 2; ni++) {
                const int c = wn * 16 + ni * 8 + fr;
                bf[ni][0] = Bs[c][k0 + fc];
                bf[ni][1] = Bs[c][k0 + fc + 4];
            }
#pragma unroll
            for (int mi = 0; mi < 2; mi++)
#pragma unroll
                for (int ni = 0; ni < 2; ni++)
                    mma16816(acc[mi][ni], af[mi], bf[ni]);
        }
        if (has_next) {
            __syncthreads();
#pragma unroll
            for (int i = 0; i < 2; i++) {
                *(uint2*)&As[arow[i]][ac2[i]] = make_uint2(pkh2(pa[i].x, pa[i].y), pkh2(pa[i].z, pa[i].w));
                *(uint2*)&Bs[arow[i]][ac2[i]] = make_uint2(pkh2(pb[i].x, pb[i].y), pkh2(pb[i].z, pb[i].w));
            }
            __syncthreads();
        }
    }
}

// ---- slim path: compute single row (row 256) as fp32 matvec -----------------
__device__ __forceinline__ void slim_row(
    const float* __restrict__ Arow, const float* __restrict__ B,
    int K, int bn, int kbeg, int klen,
    float* xs, float* outvals, int* outcols)
{
    const int tid = threadIdx.x;
    const int wid = tid >> 5, lane = tid & 31;
    const int k4 = klen >> 2;
    for (int i = tid; i < k4; i += 256)
        ((float4*)xs)[i] = ((const float4*)Arow)[i];
    __syncthreads();
#pragma unroll
    for (int cc = 0; cc < 8; cc++) {
        const int col = bn + wid * 8 + cc;
        const float4* wr = (const float4*)(B + (size_t)col * K + kbeg);
        float s = 0.f;
        for (int kb = lane; kb < k4; kb += 32) {
            const float4 w = wr[kb], xv = ((const float4*)xs)[kb];
            s += w.x * xv.x + w.y * xv.y + w.z * xv.z + w.w * xv.w;
        }
        s = warpSum(s);
        outvals[cc] = s;
        outcols[cc] = col;
    }
}

// ---- fused QKV ---------------------------------------------------------------
__global__ __launch_bounds__(256) void gemm_qkv_kernel(
    const float* __restrict__ A,
    const float* __restrict__ Wq_, const float* __restrict__ Wk_, const float* __restrict__ Wv_,
    const float* __restrict__ bq_, const float* __restrict__ bk_, const float* __restrict__ bv_,
    float* __restrict__ Q, float* __restrict__ Ko, float* __restrict__ V,
    int M, int N, int K)
{
    __shared__ uint32_t As[64][20];
    __shared__ uint32_t Bs[64][20];
    const int z = blockIdx.z;
    const float* B    = (z == 0) ? Wq_ : (z == 1) ? Wk_ : Wv_;
    const float* bias = (z == 0) ? bq_ : (z == 1) ? bk_ : bv_;
    float* C          = (z == 0) ? Q   : (z == 1) ? Ko  : V;
    const int bn = blockIdx.x * 64;

    if (blockIdx.y == 4) {   // slim: row 256 only
        float vals[8]; int cols[8];
        slim_row(A + (size_t)256 * K, B, K, bn, 0, K, (float*)As, vals, cols);
        if ((threadIdx.x & 31) == 0) {
#pragma unroll
            for (int cc = 0; cc < 8; cc++)
                C[(size_t)256 * N + cols[cc]] = vals[cc] + bias[cols[cc]];
        }
        return;
    }

    const int bm = blockIdx.y * 64;
    float acc[2][2][4] = {};
    f16_core(A, B, K, bm, bn, 0, K / 32, acc, As, Bs);

    const int lane = threadIdx.x & 31, wid = threadIdx.x >> 5;
    const int wm = wid & 1, wn = wid >> 1;
    const int fr = lane >> 2, fc = lane & 3;
#pragma unroll
    for (int mi = 0; mi < 2; mi++)
#pragma unroll
        for (int ni = 0; ni < 2; ni++) {
            const int r = bm + wm * 32 + mi * 16 + fr;
            const int c = bn + wn * 16 + ni * 8 + fc * 2;
            const float bx = bias[c], by = bias[c + 1];
            float2 o0 = {acc[mi][ni][0] + bx, acc[mi][ni][1] + by};
            float2 o1 = {acc[mi][ni][2] + bx, acc[mi][ni][3] + by};
            *(float2*)(C + (size_t)r * N + c) = o0;
            *(float2*)(C + (size_t)(r + 8) * N + c) = o1;
        }
}

// ---- direct GEMM with bias (+relu) -------------------------------------------
__global__ __launch_bounds__(256) void gemm_direct_kernel(
    const float* __restrict__ A, const float* __restrict__ B,
    const float* __restrict__ bias, float* __restrict__ C,
    int M, int N, int K, int relu_flag)
{
    __shared__ uint32_t As[64][20];
    __shared__ uint32_t Bs[64][20];
    const int bn = blockIdx.x * 64;

    if (blockIdx.y == 4) {
        float vals[8]; int cols[8];
        slim_row(A + (size_t)256 * K, B, K, bn, 0, K, (float*)As, vals, cols);
        if ((threadIdx.x & 31) == 0) {
#pragma unroll
            for (int cc = 0; cc < 8; cc++) {
                float s = vals[cc] + bias[cols[cc]];
                if (relu_flag) s = fmaxf(s, 0.f);
                C[(size_t)256 * N + cols[cc]] = s;
            }
        }
        return;
    }

    const int bm = blockIdx.y * 64;
    float acc[2][2][4] = {};
    f16_core(A, B, K, bm, bn, 0, K / 32, acc, As, Bs);

    const int lane = threadIdx.x & 31, wid = threadIdx.x >> 5;
    const int wm = wid & 1, wn = wid >> 1;
    const int fr = lane >> 2, fc = lane & 3;
#pragma unroll
    for (int mi = 0; mi < 2; mi++)
#pragma unroll
        for (int ni = 0; ni < 2; ni++) {
            const int r = bm + wm * 32 + mi * 16 + fr;
            const int c = bn + wn * 16 + ni * 8 + fc * 2;
            const float bx = bias[c], by = bias[c + 1];
            float2 o0 = {acc[mi][ni][0] + bx, acc[mi][ni][1] + by};
            float2 o1 = {acc[mi][ni][2] + bx, acc[mi][ni][3] + by};
            if (relu_flag) {
                o0.x = fmaxf(o0.x, 0.f); o0.y = fmaxf(o0.y, 0.f);
                o1.x = fmaxf(o1.x, 0.f); o1.y = fmaxf(o1.y, 0.f);
            }
            *(float2*)(C + (size_t)r * N + c) = o0;
            *(float2*)(C + (size_t)(r + 8) * N + c) = o1;
        }
}

// ---- split-K GEMM (raw partials) ---------------------------------------------
__global__ __launch_bounds__(256) void gemm_splitk_kernel(
    const float* __restrict__ A, const float* __restrict__ B,
    float* __restrict__ part, int M, int N, int K, int klen)
{
    __shared__ uint32_t As[64][20];
    __shared__ uint32_t Bs[64][20];
    const int bn = blockIdx.x * 64;
    const int z = blockIdx.z;
    float* C = part + (size_t)z * M * N;

    if (blockIdx.y == 4) {
        float vals[8]; int cols[8];
        slim_row(A + (size_t)256 * K + z * klen, B, K, bn, z * klen, klen, (float*)As, vals, cols);
        if ((threadIdx.x & 31) == 0) {
#pragma unroll
            for (int cc = 0; cc < 8; cc++)
                C[(size_t)256 * N + cols[cc]] = vals[cc];
        }
        return;
    }

    const int bm = blockIdx.y * 64;
    float acc[2][2][4] = {};
    f16_core(A, B, K, bm, bn, z * klen, klen / 32, acc, As, Bs);

    const int lane = threadIdx.x & 31, wid = threadIdx.x >> 5;
    const int wm = wid & 1, wn = wid >> 1;
    const int fr = lane >> 2, fc = lane & 3;
#pragma unroll
    for (int mi = 0; mi < 2; mi++)
#pragma unroll
        for (int ni = 0; ni < 2; ni++) {
            const int r = bm + wm * 32 + mi * 16 + fr;
            const int c = bn + wn * 16 + ni * 8 + fc * 2;
            float2 o0 = {acc[mi][ni][0], acc[mi][ni][1]};
            float2 o1 = {acc[mi][ni][2], acc[mi][ni][3]};
            *(float2*)(C + (size_t)r * N + c) = o0;
            *(float2*)(C + (size_t)(r + 8) * N + c) = o1;
        }
}

// ---- fused combine(split-K) + bias + residual + LayerNorm --------------------
__global__ __launch_bounds__(256) void combine_ln_kernel(
    const float* __restrict__ part, int KS,
    const float* __restrict__ bias, const float* __restrict__ res,
    const float* __restrict__ g, const float* __restrict__ b,
    float* __restrict__ out, int M)
{
    const int row = blockIdx.x;
    const int tid = threadIdx.x;
    const int lane = tid & 31, warp = tid >> 5;
    __shared__ float rs[8], rs2[8];
    __shared__ float smv[2];

    float4 s = ((const float4*)(part + (size_t)row * D_DIM))[tid];
    for (int z = 1; z < KS; z++) {
        const float4 t = ((const float4*)(part + ((size_t)z * M + row) * D_DIM))[tid];
        s.x += t.x; s.y += t.y; s.z += t.z; s.w += t.w;
    }
    const float4 b4 = ((const float4*)bias)[tid];
    s.x += b4.x; s.y += b4.y; s.z += b4.z; s.w += b4.w;
    const float4 r4 = ((const float4*)(res + (size_t)row * D_DIM))[tid];
    s.x += r4.x; s.y += r4.y; s.z += r4.z; s.w += r4.w;

    float sum = s.x + s.y + s.z + s.w;
    float sq = s.x * s.x + s.y * s.y + s.z * s.z + s.w * s.w;
    sum = warpSum(sum); sq = warpSum(sq);
    if (lane == 0) { rs[warp] = sum; rs2[warp] = sq; }
    __syncthreads();
    if (warp == 0) {
        float t = (lane < 8) ? rs[lane] : 0.f;
        float t2 = (lane < 8) ? rs2[lane] : 0.f;
        t = warpSum(t); t2 = warpSum(t2);
        if (lane == 0) {
            const float mean = t * (1.0f / D_DIM);
            const float var = t2 * (1.0f / D_DIM) - mean * mean;
            smv[0] = mean;
            smv[1] = rsqrtf(var + 1e-5f);
        }
    }
    __syncthreads();
    const float mean = smv[0], inv = smv[1];
    const float4 g4 = ((const float4*)g)[tid];
    const float4 be4 = ((const float4*)b)[tid];
    float4 o;
    o.x = (s.x - mean) * inv * g4.x + be4.x;
    o.y = (s.y - mean) * inv * g4.y + be4.y;
    o.z = (s.z - mean) * inv * g4.z + be4.z;
    o.w = (s.w - mean) * inv * g4.w + be4.w;
    ((float4*)(out + (size_t)row * D_DIM))[tid] = o;
}

// ---------------- attention: block per (head, 16-query tile) ----------------
#define QT 16
__global__ __launch_bounds__(256) void attn3_kernel(
    const float* __restrict__ q, const float* __restrict__ k,
    const float* __restrict__ v, float* __restrict__ o)
{
    const int h = blockIdx.x;
    const int qt = blockIdx.y * QT;
    const int tid = threadIdx.x, lane = tid & 31, warp = tid >> 5;

    __shared__ float Qs[QT][68];
    __shared__ float T[64][68];
    __shared__ float sc[QT][261];
    __shared__ float inv_s[QT];

    const int nq = min(QT, S_TOK - qt);

    {
        const int r = tid >> 4, c4 = (tid & 15) << 2;
        float4 val = (r < nq) ? *(const float4*)(q + (size_t)(qt + r) * D_DIM + h * DH + c4)
                              : make_float4(0.f, 0.f, 0.f, 0.f);
        *(float4*)&Qs[r][c4] = val;
    }

    const int qrow = tid & 15, jg = tid >> 4;

    for (int j0 = 0; j0 < S_TOK; j0 += 64) {
        const int jn = min(64, S_TOK - j0);
        __syncthreads();
#pragma unroll
        for (int i = 0; i < 4; i++) {
            const int idx = tid + i * 256;
            const int r = idx >> 4, c4 = (idx & 15) << 2;
            float4 val = (r < jn) ? *(const float4*)(k + (size_t)(j0 + r) * D_DIM + h * DH + c4)
                                  : make_float4(0.f, 0.f, 0.f, 0.f);
            *(float4*)&T[r][c4] = val;
        }
        __syncthreads();
        for (int jj = jg; jj < jn; jj += 16) {
            const float4* qr4 = (const float4*)Qs[qrow];
            const float4* kr4 = (const float4*)T[jj];
            float s = 0.f;
#pragma unroll
            for (int t = 0; t < 16; t++) {
                const float4 a = qr4[t], bb = kr4[t];
                s += a.x * bb.x + a.y * bb.y + a.z * bb.z + a.w * bb.w;
            }
            sc[qrow][j0 + jj] = s * 0.125f;
        }
    }
    __syncthreads();

#pragma unroll
    for (int ri = 0; ri < 2; ri++) {
        const int r = warp * 2 + ri;
        if (r < nq) {
            float m = -1e30f;
            for (int j = lane; j < S_TOK; j += 32) m = fmaxf(m, sc[r][j]);
            m = warpMax(m);
            float ssum = 0.f;
            for (int j = lane; j < S_TOK; j += 32) {
                const float e = __expf(sc[r][j] - m);
                sc[r][j] = e;
                ssum += e;
            }
            ssum = warpSum(ssum);
            if (lane == 0) inv_s[r] = 1.0f / ssum;
        }
    }
    __syncthreads();

    const int db = (tid >> 4) << 2;
    float4 acc = make_float4(0.f, 0.f, 0.f, 0.f);
    for (int j0 = 0; j0 < S_TOK; j0 += 64) {
        const int jn = min(64, S_TOK - j0);
        __syncthreads();
#pragma unroll
        for (int i = 0; i < 4; i++) {
            const int idx = tid + i * 256;
            const int r = idx >> 4, c4 = (idx & 15) << 2;
            float4 val = (r < jn) ? *(const float4*)(v + (size_t)(j0 + r) * D_DIM + h * DH + c4)
                                  : make_float4(0.f, 0.f, 0.f, 0.f);
            *(float4*)&T[r][c4] = val;
        }
        __syncthreads();
        for (int jj = 0; jj < jn; jj++) {
            const float w = sc[qrow][j0 + jj];
            const float4 vv = *(const float4*)&T[jj][db];
            acc.x += w * vv.x; acc.y += w * vv.y; acc.z += w * vv.z; acc.w += w * vv.w;
        }
    }
    if (qrow < nq) {
        const float iv = inv_s[qrow];
        float4 oo = {acc.x * iv, acc.y * iv, acc.z * iv, acc.w * iv};
        *(float4*)(o + (size_t)(qt + qrow) * D_DIM + h * DH + db) = oo;
    }
}

// ---------------- matvec (embeddings / heads) -------------------------------
__global__ __launch_bounds__(256) void matvec_kernel(
    const float* __restrict__ W, const float* __restrict__ bias,
    const float* __restrict__ x, float* __restrict__ out,
    int N, int K, int act)
{
    __shared__ float xs[OBS_N];
    const int tid = threadIdx.x;
    for (int i = tid; i < K; i += 256) xs[i] = x[i];
    __syncthreads();
    const int warp = tid >> 5, lane = tid & 31;
    const int n = blockIdx.x * 8 + warp;
    if (n >= N) return;
    const float4* wr = reinterpret_cast<const float4*>(W + (size_t)n * K);
    const float4* x4 = reinterpret_cast<const float4*>(xs);
    float s = 0.f;
    const int K4 = K >> 2;
    for (int kb = lane; kb < K4; kb += 32) {
        const float4 w = wr[kb], xv = x4[kb];
        s += w.x * xv.x + w.y * xv.y + w.z * xv.z + w.w * xv.w;
    }
    s = warpSum(s);
    if (lane == 0) {
        s += bias[n];
        if (act == 1) s = fmaxf(s, 0.f);
        else if (act == 2) s = tanhf(s);
        out[n] = s;
    }
}

// ---------------- concept embedding (rows 1..256 of x) ---------------------
__global__ __launch_bounds__(256) void cemb_kernel(
    const float* __restrict__ concepts, const float* __restrict__ Wc,
    const float* __restrict__ bc, const float* __restrict__ Wage,
    const float* __restrict__ bage, float* __restrict__ x)
{
    const int i = blockIdx.x;
    const int tid = threadIdx.x;
    __shared__ float cv[CSZ];
    if (tid < CSZ) cv[tid] = concepts[i * CSZ + tid];
    __syncthreads();
    const float agef = (float)i / 256.0f;
    for (int d = tid; d < D_DIM; d += 256) {
        const float4* wr = reinterpret_cast<const float4*>(Wc + (size_t)d * CSZ);
        const float4* c4 = reinterpret_cast<const float4*>(cv);
        float s = 0.f;
#pragma unroll
        for (int t = 0; t < CSZ / 4; t++) {
            const float4 w = wr[t], c = c4[t];
            s += w.x * c.x + w.y * c.y + w.z * c.z + w.w * c.w;
        }
        s += bc[d] + Wage[(size_t)d * AGE_V + i] + agef * Wage[(size_t)d * AGE_V + (AGE_V - 1)] + bage[d];
        x[(size_t)(i + 1) * D_DIM + d] = s;
    }
}

// ---------------- host launch ----------------------------------------------
extern "C" void kernel_launch(void* const* d_in, const int* in_sizes, int n_in,
                              void* d_out, int out_size)
{
    const float* observation = (const float*)d_in[0];
    const float* concepts    = (const float*)d_in[1];
    const float* W_core = (const float*)d_in[2];
    const float* b_core = (const float*)d_in[3];
    const float* W_cemb = (const float*)d_in[4];
    const float* b_cemb = (const float*)d_in[5];
    const float* W_age  = (const float*)d_in[6];
    const float* b_age  = (const float*)d_in[7];
    const float* Wq = (const float*)d_in[8];
    const float* bq = (const float*)d_in[9];
    const float* Wk = (const float*)d_in[10];
    const float* bk = (const float*)d_in[11];
    const float* Wv = (const float*)d_in[12];
    const float* bv = (const float*)d_in[13];
    const float* Wo = (const float*)d_in[14];
    const float* bo = (const float*)d_in[15];
    const float* ln1_g = (const float*)d_in[16];
    const float* ln1_b = (const float*)d_in[17];
    const float* W1 = (const float*)d_in[18];
    const float* b1 = (const float*)d_in[19];
    const float* W2 = (const float*)d_in[20];
    const float* b2 = (const float*)d_in[21];
    const float* ln2_g = (const float*)d_in[22];
    const float* ln2_b = (const float*)d_in[23];
    const float* W_concept = (const float*)d_in[24];
    const float* b_concept = (const float*)d_in[25];
    const float* W_out = (const float*)d_in[26];
    const float* b_out = (const float*)d_in[27];

    float *x, *q, *k, *v, *ao, *ffn, *part;
    cudaGetSymbolAddress((void**)&x, g_x);
    cudaGetSymbolAddress((void**)&q, g_q);
    cudaGetSymbolAddress((void**)&k, g_k);
    cudaGetSymbolAddress((void**)&v, g_v);
    cudaGetSymbolAddress((void**)&ao, g_ao);
    cudaGetSymbolAddress((void**)&ffn, g_ffn);
    cudaGetSymbolAddress((void**)&part, g_part);

    const int M = S_TOK;
    const dim3 blk(256);
    // y = 5: tiles 0..3 full (rows 0..255), tile 4 = slim path (row 256)
    const dim3 grid_qkv(D_DIM / 64, 5, 3);
    const dim3 grid_o(D_DIM / 64, 5, 2);          // split-K=2
    const dim3 grid_w1(HID / 64, 5, 1);
    const dim3 grid_w2(D_DIM / 64, 5, 4);         // split-K=4
    const dim3 grid_attn(HEADS, (S_TOK + QT - 1) / QT);   // 16 x 17

    // --- embeddings ---
    matvec_kernel<<<D_DIM / 8, 256>>>(W_core, b_core, observation, x, D_DIM, OBS_N, 0);
    cemb_kernel<<<NC, 256>>>(concepts, W_cemb, b_cemb, W_age, b_age, x);

    // --- transformer layers ---
    for (int l = 0; l < NLAYER; l++) {
        const size_t od  = (size_t)l * D_DIM * D_DIM;
        const size_t ob  = (size_t)l * D_DIM;
        const size_t o1w = (size_t)l * HID * D_DIM;
        const size_t o1b = (size_t)l * HID;

        gemm_qkv_kernel<<<grid_qkv, blk>>>(x, Wq + od, Wk + od, Wv + od,
                                           bq + ob, bk + ob, bv + ob,
                                           q, k, v, M, D_DIM, D_DIM);

        attn3_kernel<<<grid_attn, 256>>>(q, k, v, ao);

        gemm_splitk_kernel<<<grid_o, blk>>>(ao, Wo + od, part, M, D_DIM, D_DIM, D_DIM / 2);
        combine_ln_kernel<<<M, 256>>>(part, 2, bo + ob, x, ln1_g + ob, ln1_b + ob, x, M);

        gemm_direct_kernel<<<grid_w1, blk>>>(x, W1 + o1w, b1 + o1b, ffn, M, HID, D_DIM, 1);
        gemm_splitk_kernel<<<grid_w2, blk>>>(ffn, W2 + o1w, part, M, D_DIM, HID, HID / 4);
        combine_ln_kernel<<<M, 256>>>(part, 4, b2 + ob, x, ln2_g + ob, ln2_b + ob, x, M);
    }

    // --- heads (node 0) -> d_out = [output(512) | new_concept(128)] ---
    float* out = (float*)d_out;
    matvec_kernel<<<OUT_N / 8, 256>>>(W_out, b_out, x, out, OUT_N, D_DIM, 1);
    matvec_kernel<<<CSZ / 8, 256>>>(W_concept, b_concept, x, out + OUT_N, CSZ, D_DIM, 2);

    (void)in_sizes; (void)n_in; (void)out_size;
}

// round 10
// speedup vs baseline: 2.4573x; 1.0152x over previous
#include <cuda_runtime.h>
#include <math.h>
#include <stdint.h>

#define S_TOK 257
#define D_DIM 1024
#define HID 4096
#define NLAYER 12
#define NC 256
#define CSZ 128
#define AGE_V 258
#define OBS_N 2048
#define OUT_N 512
#define HEADS 16
#define DH 64

// ---------------- scratch (device globals; no allocation allowed) ----------
__device__ float g_x[S_TOK * D_DIM];
__device__ float g_q[S_TOK * D_DIM];
__device__ float g_k[S_TOK * D_DIM];
__device__ float g_v[S_TOK * D_DIM];
__device__ float g_ao[S_TOK * D_DIM];
__device__ float g_ffn[S_TOK * HID];
__device__ float g_part[4 * S_TOK * D_DIM];   // split-K partials (KS<=4)

// ---------------- helpers ---------------------------------------------------
__device__ __forceinline__ float warpMax(float v) {
#pragma unroll
    for (int o = 16; o; o >>= 1) v = fmaxf(v, __shfl_xor_sync(0xffffffffu, v, o));
    return v;
}
__device__ __forceinline__ float warpSum(float v) {
#pragma unroll
    for (int o = 16; o; o >>= 1) v += __shfl_xor_sync(0xffffffffu, v, o);
    return v;
}
__device__ __forceinline__ uint32_t pkh2(float a, float b) {   // lo=a, hi=b
    uint32_t r;
    asm("cvt.rn.f16x2.f32 %0, %1, %2;" : "=r"(r) : "f"(b), "f"(a));
    return r;
}
__device__ __forceinline__ uint32_t smem_u32p(const void* p) {
    uint32_t a;
    asm("{ .reg .u64 t; cvta.to.shared.u64 t, %1; cvt.u32.u64 %0, t; }" : "=r"(a) : "l"(p));
    return a;
}
__device__ __forceinline__ void mma16816(float (&d)[4], const uint32_t (&a)[4], const uint32_t (&b)[2]) {
    asm volatile(
        "mma.sync.aligned.m16n8k16.row.col.f32.f16.f16.f32 "
        "{%0,%1,%2,%3}, {%4,%5,%6,%7}, {%8,%9}, {%0,%1,%2,%3};\n"
        : "+f"(d[0]), "+f"(d[1]), "+f"(d[2]), "+f"(d[3])
        : "r"(a[0]), "r"(a[1]), "r"(a[2]), "r"(a[3]), "r"(b[0]), "r"(b[1]));
}
__device__ __forceinline__ void ldsm4(uint32_t& r0, uint32_t& r1, uint32_t& r2, uint32_t& r3,
                                      uint32_t addr) {
    asm volatile("ldmatrix.sync.aligned.m8n8.x4.shared.b16 {%0,%1,%2,%3}, [%4];"
                 : "=r"(r0), "=r"(r1), "=r"(r2), "=r"(r3) : "r"(addr));
}

// ============================================================================
// fp16 GEMM core with ldmatrix: C[M,N] = A[M,K] @ B[N,K]^T.
// Block 128x64, BK=32, 256 threads (8 warps 4x2, warp tile 32x32).
// Smem: half2 rows (16 data u32/row), stride 20 -> LDSM conflict-free.
// Per k16-step per warp: 2 A-LDSM.x4 + 2 B-LDSM.x4 + 8 MMA.
// ============================================================================
#define ROWW 20

__device__ __forceinline__ void f16_core128(
    const float* __restrict__ A, const float* __restrict__ B,
    int K, int bm, int bn, int kbeg, int ktiles,
    float (&acc)[2][4][4], uint32_t (*As)[ROWW], uint32_t (*Bs)[ROWW])
{
    const int tid = threadIdx.x;
    const int lane = tid & 31, wid = tid >> 5;
    const int wm = wid & 3, wn = wid >> 2;
    const int sub = lane >> 3, r8 = lane & 7;

    // ldmatrix per-lane base addresses (u32 offsets within row handled per k-step)
    const uint32_t As_b = smem_u32p(&As[0][0]);
    const uint32_t Bs_b = smem_u32p(&Bs[0][0]);
    // A: lanes 0-7 -> rows+0 +0B, 8-15 -> rows+8 +0B, 16-23 -> rows+0 +16B, 24-31 -> rows+8 +16B
    uint32_t a_addr[2];   // mi = 0,1
#pragma unroll
    for (int mi = 0; mi < 2; mi++) {
        const int row = wm * 32 + mi * 16 + (sub & 1) * 8 + r8;
        a_addr[mi] = As_b + (row * ROWW + (sub >> 1) * 4) * 4;
    }
    // B: lanes 0-7 -> n+0 +0B, 8-15 -> n+0 +16B, 16-23 -> n+8 +0B, 24-31 -> n+8 +16B
    uint32_t b_addr[2];   // p = 0,1 (16-col groups)
#pragma unroll
    for (int p = 0; p < 2; p++) {
        const int row = wn * 32 + p * 16 + (sub >> 1) * 8 + r8;
        b_addr[p] = Bs_b + (row * ROWW + (sub & 1) * 4) * 4;
    }

    // loader mapping
    int arow[4], ac2[4];
    const float* aptr[4];
#pragma unroll
    for (int i = 0; i < 4; i++) {
        const int idx = tid + i * 256;
        const int row = idx >> 3, f = idx & 7;
        arow[i] = row; ac2[i] = f * 2;
        aptr[i] = A + (size_t)(bm + row) * K + kbeg + f * 4;
    }
    int brow[2], bc2[2];
    const float* bptr[2];
#pragma unroll
    for (int i = 0; i < 2; i++) {
        const int idx = tid + i * 256;
        const int row = idx >> 3, f = idx & 7;
        brow[i] = row; bc2[i] = f * 2;
        bptr[i] = B + (size_t)(bn + row) * K + kbeg + f * 4;
    }

    float4 pa[4], pb[2];
#pragma unroll
    for (int i = 0; i < 4; i++) pa[i] = *(const float4*)(aptr[i]);
#pragma unroll
    for (int i = 0; i < 2; i++) pb[i] = *(const float4*)(bptr[i]);
#pragma unroll
    for (int i = 0; i < 4; i++)
        *(uint2*)&As[arow[i]][ac2[i]] = make_uint2(pkh2(pa[i].x, pa[i].y), pkh2(pa[i].z, pa[i].w));
#pragma unroll
    for (int i = 0; i < 2; i++)
        *(uint2*)&Bs[brow[i]][bc2[i]] = make_uint2(pkh2(pb[i].x, pb[i].y), pkh2(pb[i].z, pb[i].w));
    __syncthreads();

    for (int kt = 0; kt < ktiles; kt++) {
        const bool has_next = (kt + 1 < ktiles);
        if (has_next) {
            const int off = (kt + 1) * 32;
#pragma unroll
            for (int i = 0; i < 4; i++) pa[i] = *(const float4*)(aptr[i] + off);
#pragma unroll
            for (int i = 0; i < 2; i++) pb[i] = *(const float4*)(bptr[i] + off);
        }
#pragma unroll
        for (int ks = 0; ks < 2; ks++) {           // two k16 steps per 32-K tile
            const uint32_t koff = ks * 8 * 4;      // 8 u32 per k16
            uint32_t af[2][4], bq[2][4];
#pragma unroll
            for (int mi = 0; mi < 2; mi++)
                ldsm4(af[mi][0], af[mi][1], af[mi][2], af[mi][3], a_addr[mi] + koff);
#pragma unroll
            for (int p = 0; p < 2; p++)
                ldsm4(bq[p][0], bq[p][1], bq[p][2], bq[p][3], b_addr[p] + koff);
#pragma unroll
            for (int mi = 0; mi < 2; mi++) {
#pragma unroll
                for (int p = 0; p < 2; p++) {
                    const uint32_t b0[2] = {bq[p][0], bq[p][1]};
                    const uint32_t b1[2] = {bq[p][2], bq[p][3]};
                    mma16816(acc[mi][p * 2 + 0], af[mi], b0);
                    mma16816(acc[mi][p * 2 + 1], af[mi], b1);
                }
            }
        }
        if (has_next) {
            __syncthreads();
#pragma unroll
            for (int i = 0; i < 4; i++)
                *(uint2*)&As[arow[i]][ac2[i]] = make_uint2(pkh2(pa[i].x, pa[i].y), pkh2(pa[i].z, pa[i].w));
#pragma unroll
            for (int i = 0; i < 2; i++)
                *(uint2*)&Bs[brow[i]][bc2[i]] = make_uint2(pkh2(pb[i].x, pb[i].y), pkh2(pb[i].z, pb[i].w));
            __syncthreads();
        }
    }
}

// epilogue index helper
#define EPI128_VARS \
    const int lane = threadIdx.x & 31, wid = threadIdx.x >> 5; \
    const int wm = wid & 3, wn = wid >> 2; \
    const int fr = lane >> 2, fc = lane & 3;

// ---- slim path: compute single row (row 256) as fp32 matvec -----------------
__device__ __forceinline__ void slim_row(
    const float* __restrict__ Arow, const float* __restrict__ B,
    int K, int bn, int kbeg, int klen,
    float* xs, float* outvals, int* outcols)
{
    const int tid = threadIdx.x;
    const int wid = tid >> 5, lane = tid & 31;
    const int k4 = klen >> 2;
    for (int i = tid; i < k4; i += 256)
        ((float4*)xs)[i] = ((const float4*)Arow)[i];
    __syncthreads();
#pragma unroll
    for (int cc = 0; cc < 8; cc++) {
        const int col = bn + wid * 8 + cc;
        const float4* wr = (const float4*)(B + (size_t)col * K + kbeg);
        float s = 0.f;
        for (int kb = lane; kb < k4; kb += 32) {
            const float4 w = wr[kb], xv = ((const float4*)xs)[kb];
            s += w.x * xv.x + w.y * xv.y + w.z * xv.z + w.w * xv.w;
        }
        s = warpSum(s);
        outvals[cc] = s;
        outcols[cc] = col;
    }
}

// ---- fused QKV ---------------------------------------------------------------
__global__ __launch_bounds__(256) void gemm_qkv_kernel(
    const float* __restrict__ A,
    const float* __restrict__ Wq_, const float* __restrict__ Wk_, const float* __restrict__ Wv_,
    const float* __restrict__ bq_, const float* __restrict__ bk_, const float* __restrict__ bv_,
    float* __restrict__ Q, float* __restrict__ Ko, float* __restrict__ V,
    int M, int N, int K)
{
    __shared__ uint32_t As[128][ROWW];
    __shared__ uint32_t Bs[64][ROWW];
    const int z = blockIdx.z;
    const float* B    = (z == 0) ? Wq_ : (z == 1) ? Wk_ : Wv_;
    const float* bias = (z == 0) ? bq_ : (z == 1) ? bk_ : bv_;
    float* C          = (z == 0) ? Q   : (z == 1) ? Ko  : V;
    const int bn = blockIdx.x * 64;

    if (blockIdx.y == 2) {   // slim: row 256 only
        float vals[8]; int cols[8];
        slim_row(A + (size_t)256 * K, B, K, bn, 0, K, (float*)As, vals, cols);
        if ((threadIdx.x & 31) == 0) {
#pragma unroll
            for (int cc = 0; cc < 8; cc++)
                C[(size_t)256 * N + cols[cc]] = vals[cc] + bias[cols[cc]];
        }
        return;
    }

    const int bm = blockIdx.y * 128;
    float acc[2][4][4] = {};
    f16_core128(A, B, K, bm, bn, 0, K / 32, acc, As, Bs);

    EPI128_VARS
#pragma unroll
    for (int mi = 0; mi < 2; mi++)
#pragma unroll
        for (int ni = 0; ni < 4; ni++) {
            const int r = bm + wm * 32 + mi * 16 + fr;
            const int c = bn + wn * 32 + ni * 8 + fc * 2;
            const float bx = bias[c], by = bias[c + 1];
            float2 o0 = {acc[mi][ni][0] + bx, acc[mi][ni][1] + by};
            float2 o1 = {acc[mi][ni][2] + bx, acc[mi][ni][3] + by};
            *(float2*)(C + (size_t)r * N + c) = o0;
            *(float2*)(C + (size_t)(r + 8) * N + c) = o1;
        }
}

// ---- direct GEMM with bias (+relu) -------------------------------------------
__global__ __launch_bounds__(256) void gemm_direct_kernel(
    const float* __restrict__ A, const float* __restrict__ B,
    const float* __restrict__ bias, float* __restrict__ C,
    int M, int N, int K, int relu_flag)
{
    __shared__ uint32_t As[128][ROWW];
    __shared__ uint32_t Bs[64][ROWW];
    const int bn = blockIdx.x * 64;

    if (blockIdx.y == 2) {
        float vals[8]; int cols[8];
        slim_row(A + (size_t)256 * K, B, K, bn, 0, K, (float*)As, vals, cols);
        if ((threadIdx.x & 31) == 0) {
#pragma unroll
            for (int cc = 0; cc < 8; cc++) {
                float s = vals[cc] + bias[cols[cc]];
                if (relu_flag) s = fmaxf(s, 0.f);
                C[(size_t)256 * N + cols[cc]] = s;
            }
        }
        return;
    }

    const int bm = blockIdx.y * 128;
    float acc[2][4][4] = {};
    f16_core128(A, B, K, bm, bn, 0, K / 32, acc, As, Bs);

    EPI128_VARS
#pragma unroll
    for (int mi = 0; mi < 2; mi++)
#pragma unroll
        for (int ni = 0; ni < 4; ni++) {
            const int r = bm + wm * 32 + mi * 16 + fr;
            const int c = bn + wn * 32 + ni * 8 + fc * 2;
            const float bx = bias[c], by = bias[c + 1];
            float2 o0 = {acc[mi][ni][0] + bx, acc[mi][ni][1] + by};
            float2 o1 = {acc[mi][ni][2] + bx, acc[mi][ni][3] + by};
            if (relu_flag) {
                o0.x = fmaxf(o0.x, 0.f); o0.y = fmaxf(o0.y, 0.f);
                o1.x = fmaxf(o1.x, 0.f); o1.y = fmaxf(o1.y, 0.f);
            }
            *(float2*)(C + (size_t)r * N + c) = o0;
            *(float2*)(C + (size_t)(r + 8) * N + c) = o1;
        }
}

// ---- split-K GEMM (raw partials) ---------------------------------------------
__global__ __launch_bounds__(256) void gemm_splitk_kernel(
    const float* __restrict__ A, const float* __restrict__ B,
    float* __restrict__ part, int M, int N, int K, int klen)
{
    __shared__ uint32_t As[128][ROWW];
    __shared__ uint32_t Bs[64][ROWW];
    const int bn = blockIdx.x * 64;
    const int z = blockIdx.z;
    float* C = part + (size_t)z * M * N;

    if (blockIdx.y == 2) {
        float vals[8]; int cols[8];
        slim_row(A + (size_t)256 * K + z * klen, B, K, bn, z * klen, klen, (float*)As, vals, cols);
        if ((threadIdx.x & 31) == 0) {
#pragma unroll
            for (int cc = 0; cc < 8; cc++)
                C[(size_t)256 * N + cols[cc]] = vals[cc];
        }
        return;
    }

    const int bm = blockIdx.y * 128;
    float acc[2][4][4] = {};
    f16_core128(A, B, K, bm, bn, z * klen, klen / 32, acc, As, Bs);

    EPI128_VARS
#pragma unroll
    for (int mi = 0; mi < 2; mi++)
#pragma unroll
        for (int ni = 0; ni < 4; ni++) {
            const int r = bm + wm * 32 + mi * 16 + fr;
            const int c = bn + wn * 32 + ni * 8 + fc * 2;
            float2 o0 = {acc[mi][ni][0], acc[mi][ni][1]};
            float2 o1 = {acc[mi][ni][2], acc[mi][ni][3]};
            *(float2*)(C + (size_t)r * N + c) = o0;
            *(float2*)(C + (size_t)(r + 8) * N + c) = o1;
        }
}

// ---- fused combine(split-K) + bias + residual + LayerNorm --------------------
__global__ __launch_bounds__(256) void combine_ln_kernel(
    const float* __restrict__ part, int KS,
    const float* __restrict__ bias, const float* __restrict__ res,
    const float* __restrict__ g, const float* __restrict__ b,
    float* __restrict__ out, int M)
{
    const int row = blockIdx.x;
    const int tid = threadIdx.x;
    const int lane = tid & 31, warp = tid >> 5;
    __shared__ float rs[8], rs2[8];
    __shared__ float smv[2];

    float4 s = ((const float4*)(part + (size_t)row * D_DIM))[tid];
    for (int z = 1; z < KS; z++) {
        const float4 t = ((const float4*)(part + ((size_t)z * M + row) * D_DIM))[tid];
        s.x += t.x; s.y += t.y; s.z += t.z; s.w += t.w;
    }
    const float4 b4 = ((const float4*)bias)[tid];
    s.x += b4.x; s.y += b4.y; s.z += b4.z; s.w += b4.w;
    const float4 r4 = ((const float4*)(res + (size_t)row * D_DIM))[tid];
    s.x += r4.x; s.y += r4.y; s.z += r4.z; s.w += r4.w;

    float sum = s.x + s.y + s.z + s.w;
    float sq = s.x * s.x + s.y * s.y + s.z * s.z + s.w * s.w;
    sum = warpSum(sum); sq = warpSum(sq);
    if (lane == 0) { rs[warp] = sum; rs2[warp] = sq; }
    __syncthreads();
    if (warp == 0) {
        float t = (lane < 8) ? rs[lane] : 0.f;
        float t2 = (lane < 8) ? rs2[lane] : 0.f;
        t = warpSum(t); t2 = warpSum(t2);
        if (lane == 0) {
            const float mean = t * (1.0f / D_DIM);
            const float var = t2 * (1.0f / D_DIM) - mean * mean;
            smv[0] = mean;
            smv[1] = rsqrtf(var + 1e-5f);
        }
    }
    __syncthreads();
    const float mean = smv[0], inv = smv[1];
    const float4 g4 = ((const float4*)g)[tid];
    const float4 be4 = ((const float4*)b)[tid];
    float4 o;
    o.x = (s.x - mean) * inv * g4.x + be4.x;
    o.y = (s.y - mean) * inv * g4.y + be4.y;
    o.z = (s.z - mean) * inv * g4.z + be4.z;
    o.w = (s.w - mean) * inv * g4.w + be4.w;
    ((float4*)(out + (size_t)row * D_DIM))[tid] = o;
}

// ---------------- attention: block per (head, 16-query tile) ----------------
#define QT 16
__global__ __launch_bounds__(256) void attn3_kernel(
    const float* __restrict__ q, const float* __restrict__ k,
    const float* __restrict__ v, float* __restrict__ o)
{
    const int h = blockIdx.x;
    const int qt = blockIdx.y * QT;
    const int tid = threadIdx.x, lane = tid & 31, warp = tid >> 5;

    __shared__ float Qs[QT][68];
    __shared__ float T[64][68];
    __shared__ float sc[QT][261];
    __shared__ float inv_s[QT];

    const int nq = min(QT, S_TOK - qt);

    {
        const int r = tid >> 4, c4 = (tid & 15) << 2;
        float4 val = (r < nq) ? *(const float4*)(q + (size_t)(qt + r) * D_DIM + h * DH + c4)
                              : make_float4(0.f, 0.f, 0.f, 0.f);
        *(float4*)&Qs[r][c4] = val;
    }

    const int qrow = tid & 15, jg = tid >> 4;

    for (int j0 = 0; j0 < S_TOK; j0 += 64) {
        const int jn = min(64, S_TOK - j0);
        __syncthreads();
#pragma unroll
        for (int i = 0; i < 4; i++) {
            const int idx = tid + i * 256;
            const int r = idx >> 4, c4 = (idx & 15) << 2;
            float4 val = (r < jn) ? *(const float4*)(k + (size_t)(j0 + r) * D_DIM + h * DH + c4)
                                  : make_float4(0.f, 0.f, 0.f, 0.f);
            *(float4*)&T[r][c4] = val;
        }
        __syncthreads();
        for (int jj = jg; jj < jn; jj += 16) {
            const float4* qr4 = (const float4*)Qs[qrow];
            const float4* kr4 = (const float4*)T[jj];
            float s = 0.f;
#pragma unroll
            for (int t = 0; t < 16; t++) {
                const float4 a = qr4[t], bb = kr4[t];
                s += a.x * bb.x + a.y * bb.y + a.z * bb.z + a.w * bb.w;
            }
            sc[qrow][j0 + jj] = s * 0.125f;
        }
    }
    __syncthreads();

#pragma unroll
    for (int ri = 0; ri < 2; ri++) {
        const int r = warp * 2 + ri;
        if (r < nq) {
            float m = -1e30f;
            for (int j = lane; j < S_TOK; j += 32) m = fmaxf(m, sc[r][j]);
            m = warpMax(m);
            float ssum = 0.f;
            for (int j = lane; j < S_TOK; j += 32) {
                const float e = __expf(sc[r][j] - m);
                sc[r][j] = e;
                ssum += e;
            }
            ssum = warpSum(ssum);
            if (lane == 0) inv_s[r] = 1.0f / ssum;
        }
    }
    __syncthreads();

    const int db = (tid >> 4) << 2;
    float4 acc = make_float4(0.f, 0.f, 0.f, 0.f);
    for (int j0 = 0; j0 < S_TOK; j0 += 64) {
        const int jn = min(64, S_TOK - j0);
        __syncthreads();
#pragma unroll
        for (int i = 0; i < 4; i++) {
            const int idx = tid + i * 256;
            const int r = idx >> 4, c4 = (idx & 15) << 2;
            float4 val = (r < jn) ? *(const float4*)(v + (size_t)(j0 + r) * D_DIM + h * DH + c4)
                                  : make_float4(0.f, 0.f, 0.f, 0.f);
            *(float4*)&T[r][c4] = val;
        }
        __syncthreads();
        for (int jj = 0; jj < jn; jj++) {
            const float w = sc[qrow][j0 + jj];
            const float4 vv = *(const float4*)&T[jj][db];
            acc.x += w * vv.x; acc.y += w * vv.y; acc.z += w * vv.z; acc.w += w * vv.w;
        }
    }
    if (qrow < nq) {
        const float iv = inv_s[qrow];
        float4 oo = {acc.x * iv, acc.y * iv, acc.z * iv, acc.w * iv};
        *(float4*)(o + (size_t)(qt + qrow) * D_DIM + h * DH + db) = oo;
    }
}

// ---------------- matvec (embeddings / heads) -------------------------------
__global__ __launch_bounds__(256) void matvec_kernel(
    const float* __restrict__ W, const float* __restrict__ bias,
    const float* __restrict__ x, float* __restrict__ out,
    int N, int K, int act)
{
    __shared__ float xs[OBS_N];
    const int tid = threadIdx.x;
    for (int i = tid; i < K; i += 256) xs[i] = x[i];
    __syncthreads();
    const int warp = tid >> 5, lane = tid & 31;
    const int n = blockIdx.x * 8 + warp;
    if (n >= N) return;
    const float4* wr = reinterpret_cast<const float4*>(W + (size_t)n * K);
    const float4* x4 = reinterpret_cast<const float4*>(xs);
    float s = 0.f;
    const int K4 = K >> 2;
    for (int kb = lane; kb < K4; kb += 32) {
        const float4 w = wr[kb], xv = x4[kb];
        s += w.x * xv.x + w.y * xv.y + w.z * xv.z + w.w * xv.w;
    }
    s = warpSum(s);
    if (lane == 0) {
        s += bias[n];
        if (act == 1) s = fmaxf(s, 0.f);
        else if (act == 2) s = tanhf(s);
        out[n] = s;
    }
}

// ---------------- concept embedding (rows 1..256 of x) ---------------------
__global__ __launch_bounds__(256) void cemb_kernel(
    const float* __restrict__ concepts, const float* __restrict__ Wc,
    const float* __restrict__ bc, const float* __restrict__ Wage,
    const float* __restrict__ bage, float* __restrict__ x)
{
    const int i = blockIdx.x;
    const int tid = threadIdx.x;
    __shared__ float cv[CSZ];
    if (tid < CSZ) cv[tid] = concepts[i * CSZ + tid];
    __syncthreads();
    const float agef = (float)i / 256.0f;
    for (int d = tid; d < D_DIM; d += 256) {
        const float4* wr = reinterpret_cast<const float4*>(Wc + (size_t)d * CSZ);
        const float4* c4 = reinterpret_cast<const float4*>(cv);
        float s = 0.f;
#pragma unroll
        for (int t = 0; t < CSZ / 4; t++) {
            const float4 w = wr[t], c = c4[t];
            s += w.x * c.x + w.y * c.y + w.z * c.z + w.w * c.w;
        }
        s += bc[d] + Wage[(size_t)d * AGE_V + i] + agef * Wage[(size_t)d * AGE_V + (AGE_V - 1)] + bage[d];
        x[(size_t)(i + 1) * D_DIM + d] = s;
    }
}

// ---------------- host launch ----------------------------------------------
extern "C" void kernel_launch(void* const* d_in, const int* in_sizes, int n_in,
                              void* d_out, int out_size)
{
    const float* observation = (const float*)d_in[0];
    const float* concepts    = (const float*)d_in[1];
    const float* W_core = (const float*)d_in[2];
    const float* b_core = (const float*)d_in[3];
    const float* W_cemb = (const float*)d_in[4];
    const float* b_cemb = (const float*)d_in[5];
    const float* W_age  = (const float*)d_in[6];
    const float* b_age  = (const float*)d_in[7];
    const float* Wq = (const float*)d_in[8];
    const float* bq = (const float*)d_in[9];
    const float* Wk = (const float*)d_in[10];
    const float* bk = (const float*)d_in[11];
    const float* Wv = (const float*)d_in[12];
    const float* bv = (const float*)d_in[13];
    const float* Wo = (const float*)d_in[14];
    const float* bo = (const float*)d_in[15];
    const float* ln1_g = (const float*)d_in[16];
    const float* ln1_b = (const float*)d_in[17];
    const float* W1 = (const float*)d_in[18];
    const float* b1 = (const float*)d_in[19];
    const float* W2 = (const float*)d_in[20];
    const float* b2 = (const float*)d_in[21];
    const float* ln2_g = (const float*)d_in[22];
    const float* ln2_b = (const float*)d_in[23];
    const float* W_concept = (const float*)d_in[24];
    const float* b_concept = (const float*)d_in[25];
    const float* W_out = (const float*)d_in[26];
    const float* b_out = (const float*)d_in[27];

    float *x, *q, *k, *v, *ao, *ffn, *part;
    cudaGetSymbolAddress((void**)&x, g_x);
    cudaGetSymbolAddress((void**)&q, g_q);
    cudaGetSymbolAddress((void**)&k, g_k);
    cudaGetSymbolAddress((void**)&v, g_v);
    cudaGetSymbolAddress((void**)&ao, g_ao);
    cudaGetSymbolAddress((void**)&ffn, g_ffn);
    cudaGetSymbolAddress((void**)&part, g_part);

    const int M = S_TOK;
    const dim3 blk(256);
    // y = 3: tiles 0,1 full 128-row (rows 0..255), tile 2 = slim (row 256)
    const dim3 grid_qkv(D_DIM / 64, 3, 3);        // 144
    const dim3 grid_o(D_DIM / 64, 3, 2);          // split-K=2, 96
    const dim3 grid_w1(HID / 64, 3, 1);           // 192
    const dim3 grid_w2(D_DIM / 64, 3, 4);         // split-K=4, 192
    const dim3 grid_attn(HEADS, (S_TOK + QT - 1) / QT);   // 16 x 17

    // --- embeddings ---
    matvec_kernel<<<D_DIM / 8, 256>>>(W_core, b_core, observation, x, D_DIM, OBS_N, 0);
    cemb_kernel<<<NC, 256>>>(concepts, W_cemb, b_cemb, W_age, b_age, x);

    // --- transformer layers ---
    for (int l = 0; l < NLAYER; l++) {
        const size_t od  = (size_t)l * D_DIM * D_DIM;
        const size_t ob  = (size_t)l * D_DIM;
        const size_t o1w = (size_t)l * HID * D_DIM;
        const size_t o1b = (size_t)l * HID;

        gemm_qkv_kernel<<<grid_qkv, blk>>>(x, Wq + od, Wk + od, Wv + od,
                                           bq + ob, bk + ob, bv + ob,
                                           q, k, v, M, D_DIM, D_DIM);

        attn3_kernel<<<grid_attn, 256>>>(q, k, v, ao);

        gemm_splitk_kernel<<<grid_o, blk>>>(ao, Wo + od, part, M, D_DIM, D_DIM, D_DIM / 2);
        combine_ln_kernel<<<M, 256>>>(part, 2, bo + ob, x, ln1_g + ob, ln1_b + ob, x, M);

        gemm_direct_kernel<<<grid_w1, blk>>>(x, W1 + o1w, b1 + o1b, ffn, M, HID, D_DIM, 1);
        gemm_splitk_kernel<<<grid_w2, blk>>>(ffn, W2 + o1w, part, M, D_DIM, HID, HID / 4);
        combine_ln_kernel<<<M, 256>>>(part, 4, b2 + ob, x, ln2_g + ob, ln2_b + ob, x, M);
    }

    // --- heads (node 0) -> d_out = [output(512) | new_concept(128)] ---
    float* out = (float*)d_out;
    matvec_kernel<<<OUT_N / 8, 256>>>(W_out, b_out, x, out, OUT_N, D_DIM, 1);
    matvec_kernel<<<CSZ / 8, 256>>>(W_concept, b_concept, x, out + OUT_N, CSZ, D_DIM, 2);

    (void)in_sizes; (void)n_in; (void)out_size;
}